// round 5
// baseline (speedup 1.0000x reference)
#include <cuda_runtime.h>

// Problem constants
#define NB  4
#define NN  4096   // H*W
#define NC  256
#define NCP 128

// Scratch for K, Q, V projections (8 MB each). Static __device__ arrays are the
// sanctioned scratch mechanism (no allocations allowed anywhere).
static __device__ float g_K[NB * NN * NCP];
static __device__ float g_Q[NB * NN * NCP];
static __device__ float g_V[NB * NN * NCP];

typedef unsigned long long u64;

// ---- packed f32x2 helpers (Blackwell sm_103a: FFMA2 only reachable via PTX) ----
__device__ __forceinline__ u64 pack2(float lo, float hi) {
    u64 r; asm("mov.b64 %0, {%1, %2};" : "=l"(r) : "f"(lo), "f"(hi)); return r;
}
__device__ __forceinline__ float2 unpack2(u64 v) {
    float2 r; asm("mov.b64 {%0, %1}, %2;" : "=f"(r.x), "=f"(r.y) : "l"(v)); return r;
}
__device__ __forceinline__ u64 ffma2(u64 a, u64 b, u64 c) {
    u64 d; asm("fma.rn.f32x2 %0, %1, %2, %3;" : "=l"(d) : "l"(a), "l"(b), "l"(c)); return d;
}
__device__ __forceinline__ u64 fmul2(u64 a, u64 b) {
    u64 d; asm("mul.rn.f32x2 %0, %1, %2;" : "=l"(d) : "l"(a), "l"(b)); return d;
}

// ============================================================================
// Kernel 1: fused projections. Y = X @ W + b for the 4 weight sets.
//   grid = (16384/64, 4): blockIdx.y selects {K, Q, V, shortcut}.
//   CTA tile 64x128, BK=32, 256 threads, 4x(4x2) register tile, FFMA2 inner.
//   Shortcut (sel==3) is written straight into d_out; attention adds onto it.
// ============================================================================
__global__ void __launch_bounds__(256, 2) proj_kernel(
    const float* __restrict__ X,
    const float* __restrict__ Wk, const float* __restrict__ bk,
    const float* __restrict__ Wq, const float* __restrict__ bq,
    const float* __restrict__ Wv, const float* __restrict__ bv,
    const float* __restrict__ Ws, const float* __restrict__ bs,
    float* __restrict__ OutS)
{
    __shared__ float Xs[64][36];     // pad 36: float4 STS aligned, broadcast reads
    __shared__ float Wsh[32][128];   // even stride: 2*tx bank pattern, conflict-free

    const int sel = blockIdx.y;
    const float* W   = (sel == 0) ? Wk : (sel == 1) ? Wq : (sel == 2) ? Wv : Ws;
    const float* bia = (sel == 0) ? bk : (sel == 1) ? bq : (sel == 2) ? bv : bs;
    float* Y         = (sel == 0) ? g_K : (sel == 1) ? g_Q : (sel == 2) ? g_V : OutS;

    const int tid = threadIdx.x;
    const int tx = tid & 15, ty = tid >> 4;
    const int rowBase = blockIdx.x * 64;

    u64 acc[4][4];
#pragma unroll
    for (int i = 0; i < 4; i++)
#pragma unroll
        for (int j = 0; j < 4; j++) acc[i][j] = 0ull;

    for (int kc = 0; kc < NC; kc += 32) {
#pragma unroll
        for (int u = 0; u < 2; u++) {                 // X tile 64x32
            int idx = tid + u * 256;
            int r = idx >> 3, c4 = idx & 7;
            float4 v = *(const float4*)(X + (size_t)(rowBase + r) * NC + kc + c4 * 4);
            *(float4*)(&Xs[r][c4 * 4]) = v;
        }
#pragma unroll
        for (int u = 0; u < 4; u++) {                 // W tile 32x128
            int idx = tid + u * 256;
            int r = idx >> 5, c4 = idx & 31;
            float4 v = *(const float4*)(W + (size_t)(kc + r) * NCP + c4 * 4);
            *(float4*)(&Wsh[r][c4 * 4]) = v;
        }
        __syncthreads();
#pragma unroll
        for (int kk = 0; kk < 32; kk++) {
            u64 w2[4];
#pragma unroll
            for (int j = 0; j < 4; j++)
                w2[j] = *(const u64*)(&Wsh[kk][2 * (tx + 16 * j)]);
#pragma unroll
            for (int i = 0; i < 4; i++) {
                float xv = Xs[ty * 4 + i][kk];
                u64 x2 = pack2(xv, xv);
#pragma unroll
                for (int j = 0; j < 4; j++)
                    acc[i][j] = ffma2(x2, w2[j], acc[i][j]);
            }
        }
        __syncthreads();
    }

#pragma unroll
    for (int j = 0; j < 4; j++) {
        int p = tx + 16 * j;
        float2 bb = *(const float2*)(bia + 2 * p);
#pragma unroll
        for (int i = 0; i < 4; i++) {
            float2 v = unpack2(acc[i][j]);
            v.x += bb.x; v.y += bb.y;
            *(float2*)(Y + (size_t)(rowBase + ty * 4 + i) * NCP + 2 * p) = v;
        }
    }
}

// ============================================================================
// Kernel 2: flash attention, fp32 FFMA2.
//   Roles per the reference: "query" = K rows, "key" = Q rows, value = V.
//   BR=32 query rows per CTA, BC=64 keys per step, d=128, 256 threads.
//   smem 90,880 B -> 2 CTAs/SM. Thread (tx,ty): rows {2ty, 2ty+1},
//   score cols {tx+16j}, O col-pairs {tx+16j} (strided mapping makes every
//   LDS.64 bank pattern 2*tx -> conflict-free; Qs stride 130 keeps that true
//   for the k-vectorized score reads).
//   Out already holds the shortcut; final write adds O/l onto it.
// ============================================================================
#define ATTN_SMEM_FLOATS (32 * 128 + 64 * 130 + 64 * 128 + 32 * 66)
#define ATTN_SMEM_BYTES  (ATTN_SMEM_FLOATS * 4)

__global__ void __launch_bounds__(256, 2) attn_kernel(float* __restrict__ Out)
{
    extern __shared__ float sm[];
    float* Kq = sm;                  // [32][128] query-role rows (K matrix)
    float* Qs = Kq + 32 * 128;       // [64][130] key-role tile (Q matrix), padded
    float* Vs = Qs + 64 * 130;       // [64][128]
    float* Ps = Vs + 64 * 128;       // [32][66]  softmax probabilities

    const int tid = threadIdx.x;
    const int tx = tid & 15, ty = tid >> 4;
    const int b  = blockIdx.y;
    const int rb = blockIdx.x;       // 0..127

    const float* Kbase = g_K + ((size_t)b * NN + rb * 32) * NCP;
    const float* Qbase = g_Q + (size_t)b * NN * NCP;
    const float* Vbase = g_V + (size_t)b * NN * NCP;

#pragma unroll
    for (int u = 0; u < 4; u++) {                 // load Kq once (32x128)
        int idx = tid + u * 256;
        int r = idx >> 5, c4 = idx & 31;
        *(float4*)(Kq + r * 128 + c4 * 4) = *(const float4*)(Kbase + r * NCP + c4 * 4);
    }

    u64 o2[2][4];
#pragma unroll
    for (int i = 0; i < 2; i++)
#pragma unroll
        for (int j = 0; j < 4; j++) o2[i][j] = 0ull;
    float m_[2] = { -1e30f, -1e30f };             // finite sentinel: avoids inf-inf
    float l_[2] = { 0.f, 0.f };

    for (int jb = 0; jb < NN / 64; jb++) {
        const float* Qt = Qbase + (size_t)jb * 64 * NCP;
        const float* Vt = Vbase + (size_t)jb * 64 * NCP;

        __syncthreads();   // previous iter's consumers done before overwrite
#pragma unroll
        for (int u = 0; u < 16; u++) {            // Qs: 64x64 float2, stride 130
            int idx = tid + u * 256;
            int r = idx >> 6, c2 = idx & 63;
            *(float2*)(Qs + r * 130 + c2 * 2) = *(const float2*)(Qt + r * NCP + c2 * 2);
        }
#pragma unroll
        for (int u = 0; u < 8; u++) {             // Vs: 64x128
            int idx = tid + u * 256;
            int r = idx >> 5, c4 = idx & 31;
            *(float4*)(Vs + r * 128 + c4 * 4) = *(const float4*)(Vt + r * NCP + c4 * 4);
        }
        __syncthreads();

        // ---- S = Kq @ Qs^T over d=128, f32x2-packed along k ----
        u64 s2[2][4];
#pragma unroll
        for (int i = 0; i < 2; i++)
#pragma unroll
            for (int j = 0; j < 4; j++) s2[i][j] = 0ull;
#pragma unroll 16
        for (int kp = 0; kp < 64; kp++) {
            u64 q2[4], kq2[2];
#pragma unroll
            for (int j = 0; j < 4; j++)
                q2[j] = *(const u64*)(Qs + (tx + 16 * j) * 130 + 2 * kp);
#pragma unroll
            for (int i = 0; i < 2; i++)
                kq2[i] = *(const u64*)(Kq + (ty * 2 + i) * 128 + 2 * kp);
#pragma unroll
            for (int i = 0; i < 2; i++)
#pragma unroll
                for (int j = 0; j < 4; j++)
                    s2[i][j] = ffma2(kq2[i], q2[j], s2[i][j]);
        }

        // ---- online softmax (row groups = 16 tx lanes, shfl_xor stays in-half) ----
#pragma unroll
        for (int i = 0; i < 2; i++) {
            float s[4];
#pragma unroll
            for (int j = 0; j < 4; j++) {
                float2 t = unpack2(s2[i][j]);
                s[j] = t.x + t.y;
            }
            float mx = fmaxf(fmaxf(s[0], s[1]), fmaxf(s[2], s[3]));
#pragma unroll
            for (int msk = 8; msk >= 1; msk >>= 1)
                mx = fmaxf(mx, __shfl_xor_sync(0xffffffffu, mx, msk));
            float mnew = fmaxf(m_[i], mx);
            float sum = 0.f;
#pragma unroll
            for (int j = 0; j < 4; j++) {
                float p = __expf(s[j] - mnew);
                Ps[(ty * 2 + i) * 66 + tx + 16 * j] = p;
                sum += p;
            }
#pragma unroll
            for (int msk = 8; msk >= 1; msk >>= 1)
                sum += __shfl_xor_sync(0xffffffffu, sum, msk);
            float alpha = __expf(m_[i] - mnew);
            l_[i] = l_[i] * alpha + sum;
            m_[i] = mnew;
            u64 a2 = pack2(alpha, alpha);
#pragma unroll
            for (int j = 0; j < 4; j++)
                o2[i][j] = fmul2(a2, o2[i][j]);
        }
        __syncthreads();   // Ps visible to all lanes

        // ---- O += P @ V, f32x2-packed along output columns ----
#pragma unroll 16
        for (int kk = 0; kk < 64; kk++) {
            u64 v2[4];
#pragma unroll
            for (int j = 0; j < 4; j++)
                v2[j] = *(const u64*)(Vs + kk * 128 + 2 * (tx + 16 * j));
#pragma unroll
            for (int i = 0; i < 2; i++) {
                float p = Ps[(ty * 2 + i) * 66 + kk];   // broadcast
                u64 p2 = pack2(p, p);
#pragma unroll
                for (int j = 0; j < 4; j++)
                    o2[i][j] = ffma2(p2, v2[j], o2[i][j]);
            }
        }
    }

    // ---- epilogue: out = O / l + shortcut (shortcut pre-written into Out) ----
#pragma unroll
    for (int i = 0; i < 2; i++) {
        float inv = 1.0f / l_[i];
        size_t rowoff = ((size_t)b * NN + rb * 32 + ty * 2 + i) * NCP;
#pragma unroll
        for (int j = 0; j < 4; j++) {
            int p = tx + 16 * j;
            float2 o = unpack2(o2[i][j]);
            float2 sc = *(const float2*)(Out + rowoff + 2 * p);
            o.x = o.x * inv + sc.x;
            o.y = o.y * inv + sc.y;
            *(float2*)(Out + rowoff + 2 * p) = o;
        }
    }
}

// ============================================================================
// Launch
// ============================================================================
extern "C" void kernel_launch(void* const* d_in, const int* in_sizes, int n_in,
                              void* d_out, int out_size) {
    (void)in_sizes; (void)n_in; (void)out_size;
    const float* x  = (const float*)d_in[0];
    const float* Wk = (const float*)d_in[1];
    const float* bk = (const float*)d_in[2];
    const float* Wq = (const float*)d_in[3];
    const float* bq = (const float*)d_in[4];
    const float* Wv = (const float*)d_in[5];
    const float* bv = (const float*)d_in[6];
    const float* Ws = (const float*)d_in[7];
    const float* bs = (const float*)d_in[8];
    float* out = (float*)d_out;

    // Idempotent, legal during capture (not a stream op, not an allocation).
    cudaFuncSetAttribute(attn_kernel,
                         cudaFuncAttributeMaxDynamicSharedMemorySize,
                         ATTN_SMEM_BYTES);

    // K, Q, V -> scratch; shortcut -> d_out (attention adds onto it).
    proj_kernel<<<dim3(NB * NN / 64, 4), 256>>>(x, Wk, bk, Wq, bq, Wv, bv, Ws, bs, out);

    // Flash attention: 128 row-blocks x 4 batches.
    attn_kernel<<<dim3(NN / 32, NB), 256, ATTN_SMEM_BYTES>>>(out);
}

// round 6
// speedup vs baseline: 1.4312x; 1.4312x over previous
#include <cuda_runtime.h>

// Problem constants
#define NB  4
#define NN  4096   // H*W
#define NC  256
#define NCP 128

// Scratch (static __device__ arrays: the sanctioned no-alloc scratch mechanism).
static __device__ float g_K [NB * NN * NCP];
static __device__ float g_Q [NB * NN * NCP];
static __device__ float g_V [NB * NN * NCP];
static __device__ float g_Qt[NB * NCP * NN];   // Q transposed: [b][c'][n]

typedef unsigned long long u64;

// ---- packed f32x2 helpers (FFMA2 only reachable via PTX on sm_103a) ----
__device__ __forceinline__ u64 pack2(float lo, float hi) {
    u64 r; asm("mov.b64 %0, {%1, %2};" : "=l"(r) : "f"(lo), "f"(hi)); return r;
}
__device__ __forceinline__ float2 unpack2(u64 v) {
    float2 r; asm("mov.b64 {%0, %1}, %2;" : "=f"(r.x), "=f"(r.y) : "l"(v)); return r;
}
__device__ __forceinline__ u64 ffma2(u64 a, u64 b, u64 c) {
    u64 d; asm("fma.rn.f32x2 %0, %1, %2, %3;" : "=l"(d) : "l"(a), "l"(b), "l"(c)); return d;
}
__device__ __forceinline__ u64 fmul2(u64 a, u64 b) {
    u64 d; asm("mul.rn.f32x2 %0, %1, %2;" : "=l"(d) : "l"(a), "l"(b)); return d;
}

// ============================================================================
// Kernel 1: fused projections (unchanged from R5 — ~93us, not the bottleneck).
// ============================================================================
__global__ void __launch_bounds__(256, 2) proj_kernel(
    const float* __restrict__ X,
    const float* __restrict__ Wk, const float* __restrict__ bk,
    const float* __restrict__ Wq, const float* __restrict__ bq,
    const float* __restrict__ Wv, const float* __restrict__ bv,
    const float* __restrict__ Ws, const float* __restrict__ bs,
    float* __restrict__ OutS)
{
    __shared__ float Xs[64][36];
    __shared__ float Wsh[32][128];

    const int sel = blockIdx.y;
    const float* W   = (sel == 0) ? Wk : (sel == 1) ? Wq : (sel == 2) ? Wv : Ws;
    const float* bia = (sel == 0) ? bk : (sel == 1) ? bq : (sel == 2) ? bv : bs;
    float* Y         = (sel == 0) ? g_K : (sel == 1) ? g_Q : (sel == 2) ? g_V : OutS;

    const int tid = threadIdx.x;
    const int tx = tid & 15, ty = tid >> 4;
    const int rowBase = blockIdx.x * 64;

    u64 acc[4][4];
#pragma unroll
    for (int i = 0; i < 4; i++)
#pragma unroll
        for (int j = 0; j < 4; j++) acc[i][j] = 0ull;

    for (int kc = 0; kc < NC; kc += 32) {
#pragma unroll
        for (int u = 0; u < 2; u++) {
            int idx = tid + u * 256;
            int r = idx >> 3, c4 = idx & 7;
            float4 v = *(const float4*)(X + (size_t)(rowBase + r) * NC + kc + c4 * 4);
            *(float4*)(&Xs[r][c4 * 4]) = v;
        }
#pragma unroll
        for (int u = 0; u < 4; u++) {
            int idx = tid + u * 256;
            int r = idx >> 5, c4 = idx & 31;
            float4 v = *(const float4*)(W + (size_t)(kc + r) * NCP + c4 * 4);
            *(float4*)(&Wsh[r][c4 * 4]) = v;
        }
        __syncthreads();
#pragma unroll
        for (int kk = 0; kk < 32; kk++) {
            u64 w2[4];
#pragma unroll
            for (int j = 0; j < 4; j++)
                w2[j] = *(const u64*)(&Wsh[kk][2 * (tx + 16 * j)]);
#pragma unroll
            for (int i = 0; i < 4; i++) {
                float xv = Xs[ty * 4 + i][kk];
                u64 x2 = pack2(xv, xv);
#pragma unroll
                for (int j = 0; j < 4; j++)
                    acc[i][j] = ffma2(x2, w2[j], acc[i][j]);
            }
        }
        __syncthreads();
    }

#pragma unroll
    for (int j = 0; j < 4; j++) {
        int p = tx + 16 * j;
        float2 bb = *(const float2*)(bia + 2 * p);
#pragma unroll
        for (int i = 0; i < 4; i++) {
            float2 v = unpack2(acc[i][j]);
            v.x += bb.x; v.y += bb.y;
            *(float2*)(Y + (size_t)(rowBase + ty * 4 + i) * NCP + 2 * p) = v;
        }
    }
}

// ============================================================================
// Kernel 1.5: transpose Q -> Qt ([b][n][c'] -> [b][c'][n]). ~8MB moved, ~10us.
// ============================================================================
__global__ void transpose_q_kernel()
{
    __shared__ float t[32][33];
    const int b  = blockIdx.z;
    const int n0 = blockIdx.x * 32;
    const int c0 = blockIdx.y * 32;
    const int tx = threadIdx.x, ty = threadIdx.y;   // 32 x 8

#pragma unroll
    for (int u = 0; u < 4; u++)
        t[ty * 4 + u][tx] = g_Q[((size_t)b * NN + n0 + ty * 4 + u) * NCP + c0 + tx];
    __syncthreads();
#pragma unroll
    for (int u = 0; u < 4; u++)
        g_Qt[((size_t)b * NCP + c0 + ty * 4 + u) * NN + n0 + tx] = t[tx][ty * 4 + u];
}

// ============================================================================
// Kernel 2: flash attention, fp32 FFMA2, column-packed operands.
//   BR=64 query rows (K matrix) per CTA, BC=64 keys (Q matrix) per step, d=128.
//   256 threads (16 tx x 16 ty). Thread: rows {4ty+i}, score col-pairs {tx+16j, j<2},
//   O col-pairs {tx+16j, j<4}.
//   Score inner: QsT LDS.64 feeds 2 cols, K broadcast duplicated via pack ->
//     16 FFMA2 per 8 LDS (+12 ALU). PV inner: 32 FFMA2 per 12 LDS.
//   Smem 99KB -> 2 CTA/SM; grid 256 CTAs -> fully resident, zero wave tail.
//   Ps aliases the QsT buffer (disjoint in time).
// ============================================================================
#define KQ_S 132   // Kq stride: 4-row bank spread (4*132 mod 32 = 16), float4-aligned
#define QT_S 68    // QsT/Ps stride: even (u64-aligned), multiple of 4 (float4 STS)
#define VS_S 128
#define ATTN_SMEM_BYTES ((64 * KQ_S + 128 * QT_S + 64 * VS_S) * 4)   // 101376 B

__global__ void __launch_bounds__(256, 2) attn_kernel(float* __restrict__ Out)
{
    extern __shared__ float sm[];
    float* Kq  = sm;                    // [64][132] query rows (K matrix)
    float* QsT = Kq + 64 * KQ_S;        // [128][68] key tile transposed (Q matrix)
    float* Vs  = QsT + 128 * QT_S;      // [64][128]
    float* Ps  = QsT;                   // [64][68] aliased — guarded by syncs

    const int tid = threadIdx.x;
    const int tx = tid & 15, ty = tid >> 4;
    const int b  = blockIdx.y;
    const int rb = blockIdx.x;          // 0..63

    // Load this CTA's 64 query rows once.
    const float* Kbase = g_K + ((size_t)b * NN + rb * 64) * NCP;
#pragma unroll
    for (int u = 0; u < 8; u++) {
        int idx = tid + u * 256;
        int r = idx >> 5, c4 = idx & 31;
        *(float4*)(Kq + r * KQ_S + c4 * 4) = *(const float4*)(Kbase + r * NCP + c4 * 4);
    }

    u64 o2[4][4];
#pragma unroll
    for (int i = 0; i < 4; i++)
#pragma unroll
        for (int j = 0; j < 4; j++) o2[i][j] = 0ull;
    float m_[4] = { -1e30f, -1e30f, -1e30f, -1e30f };
    float l_[4] = { 0.f, 0.f, 0.f, 0.f };

    const float* Qtb = g_Qt + (size_t)b * NCP * NN;
    const float* Vb  = g_V  + (size_t)b * NN * NCP;

    for (int jb = 0; jb < NN / 64; jb++) {
        __syncthreads();   // previous iter's PV (Ps, Vs readers) done
#pragma unroll
        for (int u = 0; u < 8; u++) {            // QsT tile: 128 k x 64 c
            int idx = tid + u * 256;
            int k = idx >> 4, c4 = idx & 15;
            float4 v = *(const float4*)(Qtb + (size_t)k * NN + jb * 64 + c4 * 4);
            *(float4*)(QsT + k * QT_S + c4 * 4) = v;
        }
#pragma unroll
        for (int u = 0; u < 8; u++) {            // Vs tile: 64 x 128
            int idx = tid + u * 256;
            int r = idx >> 5, c4 = idx & 31;
            float4 v = *(const float4*)(Vb + ((size_t)jb * 64 + r) * NCP + c4 * 4);
            *(float4*)(Vs + r * VS_S + c4 * 4) = v;
        }
        __syncthreads();

        // ---- scores: S[r][c] = sum_k Kq[r][k] * QsT[k][c], col-pair packed ----
        u64 s2[4][2];
#pragma unroll
        for (int i = 0; i < 4; i++) { s2[i][0] = 0ull; s2[i][1] = 0ull; }
#pragma unroll 2
        for (int kp = 0; kp < 64; kp++) {        // k = 2kp, 2kp+1
            u64 q0[2], q1[2], kk2[4];
#pragma unroll
            for (int j = 0; j < 2; j++) {
                q0[j] = *(const u64*)(QsT + (2 * kp)     * QT_S + 2 * (tx + 16 * j));
                q1[j] = *(const u64*)(QsT + (2 * kp + 1) * QT_S + 2 * (tx + 16 * j));
            }
#pragma unroll
            for (int i = 0; i < 4; i++)
                kk2[i] = *(const u64*)(Kq + (4 * ty + i) * KQ_S + 2 * kp);
#pragma unroll
            for (int i = 0; i < 4; i++) {
                float2 kv = unpack2(kk2[i]);
                u64 a0 = pack2(kv.x, kv.x);
                u64 a1 = pack2(kv.y, kv.y);
#pragma unroll
                for (int j = 0; j < 2; j++) {
                    s2[i][j] = ffma2(a0, q0[j], s2[i][j]);
                    s2[i][j] = ffma2(a1, q1[j], s2[i][j]);
                }
            }
        }
        __syncthreads();   // all warps done reading QsT before Ps overwrites it

        // ---- online softmax: row spread across 16 tx lanes ----
#pragma unroll
        for (int i = 0; i < 4; i++) {
            float2 p0 = unpack2(s2[i][0]);
            float2 p1 = unpack2(s2[i][1]);
            float mx = fmaxf(fmaxf(p0.x, p0.y), fmaxf(p1.x, p1.y));
#pragma unroll
            for (int msk = 8; msk; msk >>= 1)
                mx = fmaxf(mx, __shfl_xor_sync(0xffffffffu, mx, msk));
            float mnew = fmaxf(m_[i], mx);
            p0.x = __expf(p0.x - mnew); p0.y = __expf(p0.y - mnew);
            p1.x = __expf(p1.x - mnew); p1.y = __expf(p1.y - mnew);
            int r = 4 * ty + i;
            *(float2*)(Ps + r * QT_S + 2 * tx)        = p0;
            *(float2*)(Ps + r * QT_S + 2 * (tx + 16)) = p1;
            float sum = p0.x + p0.y + p1.x + p1.y;
#pragma unroll
            for (int msk = 8; msk; msk >>= 1)
                sum += __shfl_xor_sync(0xffffffffu, sum, msk);
            float alpha = __expf(m_[i] - mnew);
            l_[i] = l_[i] * alpha + sum;
            m_[i] = mnew;
            u64 a2 = pack2(alpha, alpha);
#pragma unroll
            for (int j = 0; j < 4; j++)
                o2[i][j] = fmul2(a2, o2[i][j]);
        }
        __syncthreads();   // Ps visible

        // ---- O += P @ V ----
#pragma unroll 2
        for (int kp = 0; kp < 32; kp++) {        // kk = 2kp, 2kp+1
            u64 v0[4], v1[4], pp[4];
#pragma unroll
            for (int j = 0; j < 4; j++) {
                v0[j] = *(const u64*)(Vs + (2 * kp)     * VS_S + 2 * (tx + 16 * j));
                v1[j] = *(const u64*)(Vs + (2 * kp + 1) * VS_S + 2 * (tx + 16 * j));
            }
#pragma unroll
            for (int i = 0; i < 4; i++)
                pp[i] = *(const u64*)(Ps + (4 * ty + i) * QT_S + 2 * kp);
#pragma unroll
            for (int i = 0; i < 4; i++) {
                float2 pv = unpack2(pp[i]);
                u64 a0 = pack2(pv.x, pv.x);
                u64 a1 = pack2(pv.y, pv.y);
#pragma unroll
                for (int j = 0; j < 4; j++) {
                    o2[i][j] = ffma2(a0, v0[j], o2[i][j]);
                    o2[i][j] = ffma2(a1, v1[j], o2[i][j]);
                }
            }
        }
    }

    // ---- epilogue: out = O / l + shortcut (shortcut pre-written into Out) ----
#pragma unroll
    for (int i = 0; i < 4; i++) {
        float inv = 1.0f / l_[i];
        int n = rb * 64 + 4 * ty + i;
        float* orow = Out + ((size_t)b * NN + n) * NCP;
#pragma unroll
        for (int j = 0; j < 4; j++) {
            int c = 2 * (tx + 16 * j);
            float2 sc = *(const float2*)(orow + c);
            float2 o = unpack2(o2[i][j]);
            o.x = o.x * inv + sc.x;
            o.y = o.y * inv + sc.y;
            *(float2*)(orow + c) = o;
        }
    }
}

// ============================================================================
// Launch
// ============================================================================
extern "C" void kernel_launch(void* const* d_in, const int* in_sizes, int n_in,
                              void* d_out, int out_size) {
    (void)in_sizes; (void)n_in; (void)out_size;
    const float* x  = (const float*)d_in[0];
    const float* Wk = (const float*)d_in[1];
    const float* bk = (const float*)d_in[2];
    const float* Wq = (const float*)d_in[3];
    const float* bq = (const float*)d_in[4];
    const float* Wv = (const float*)d_in[5];
    const float* bv = (const float*)d_in[6];
    const float* Ws = (const float*)d_in[7];
    const float* bs = (const float*)d_in[8];
    float* out = (float*)d_out;

    cudaFuncSetAttribute(attn_kernel,
                         cudaFuncAttributeMaxDynamicSharedMemorySize,
                         ATTN_SMEM_BYTES);

    // K, Q, V -> scratch; shortcut -> d_out (attention adds onto it).
    proj_kernel<<<dim3(NB * NN / 64, 4), 256>>>(x, Wk, bk, Wq, bq, Wv, bv, Ws, bs, out);

    // Q -> Qt (column-major keys for the column-packed score loop).
    transpose_q_kernel<<<dim3(NN / 32, NCP / 32, NB), dim3(32, 8)>>>();

    // Flash attention: 64 row-blocks x 4 batches = 256 CTAs, all resident at 2/SM.
    attn_kernel<<<dim3(NN / 64, NB), 256, ATTN_SMEM_BYTES>>>(out);
}

// round 8
// speedup vs baseline: 2.9047x; 2.0295x over previous
#include <cuda_runtime.h>
#include <cuda_bf16.h>
#include <cstdint>

// Problem constants
#define NB  4
#define NN  4096   // H*W
#define NC  256
#define NCP 128

// Scratch (static __device__ arrays: the sanctioned no-alloc scratch mechanism).
static __device__ float          g_V  [NB * NN * NCP];       // fp32 V
static __device__ __nv_bfloat16  g_Khi[NB * NN * NCP];       // K split hi/lo  [b*NN+n][c]
static __device__ __nv_bfloat16  g_Klo[NB * NN * NCP];
static __device__ __nv_bfloat16  g_Qhi[NB * NN * NCP];       // Q split hi/lo
static __device__ __nv_bfloat16  g_Qlo[NB * NN * NCP];
static __device__ __nv_bfloat16  g_Vthi[NB * NCP * NN];      // V^T split  [b*NCP+c][n]
static __device__ __nv_bfloat16  g_Vtlo[NB * NCP * NN];
static __device__ float          g_S [NB * NN * NN];         // scores (256 MB)
static __device__ float          g_Ms[NB * NN];              // row max
static __device__ float          g_Li[NB * NN];              // 1 / row sumexp

typedef unsigned long long u64;

// ---- packed f32x2 helpers (proj kernel) ----
__device__ __forceinline__ u64 pack2(float lo, float hi) {
    u64 r; asm("mov.b64 %0, {%1, %2};" : "=l"(r) : "f"(lo), "f"(hi)); return r;
}
__device__ __forceinline__ float2 unpack2(u64 v) {
    float2 r; asm("mov.b64 {%0, %1}, %2;" : "=f"(r.x), "=f"(r.y) : "l"(v)); return r;
}
__device__ __forceinline__ u64 ffma2(u64 a, u64 b, u64 c) {
    u64 d; asm("fma.rn.f32x2 %0, %1, %2, %3;" : "=l"(d) : "l"(a), "l"(b), "l"(c)); return d;
}

// ---- bf16 split + pack helpers ----
__device__ __forceinline__ void bsplit(float x, __nv_bfloat16& h, __nv_bfloat16& l) {
    h = __float2bfloat16(x);
    l = __float2bfloat16(x - __bfloat162float(h));
}
__device__ __forceinline__ uint32_t pk(__nv_bfloat16 a, __nv_bfloat16 b) {
    return (uint32_t)__bfloat16_as_ushort(a) | ((uint32_t)__bfloat16_as_ushort(b) << 16);
}

// ---- warp MMA: m16n8k16, row.col, bf16 inputs, fp32 accumulate (baseline PTX, sm_80+) ----
__device__ __forceinline__ void mma_bf16(float c[4], uint32_t a0, uint32_t a1,
                                         uint32_t a2, uint32_t a3,
                                         uint32_t b0, uint32_t b1) {
    asm volatile("mma.sync.aligned.m16n8k16.row.col.f32.bf16.bf16.f32 "
        "{%0,%1,%2,%3}, {%4,%5,%6,%7}, {%8,%9}, {%0,%1,%2,%3};"
        : "+f"(c[0]), "+f"(c[1]), "+f"(c[2]), "+f"(c[3])
        : "r"(a0), "r"(a1), "r"(a2), "r"(a3), "r"(b0), "r"(b1));
}

#define SKS 72   // smem tile stride in bf16 elems: (36g + q) % 32 distinct -> conflict-free frags

// ============================================================================
// Kernel 1: fused projections. K,Q written as bf16 hi/lo splits; V fp32;
//           shortcut -> Out fp32.
// ============================================================================
__global__ void __launch_bounds__(256, 2) proj_kernel(
    const float* __restrict__ X,
    const float* __restrict__ Wk, const float* __restrict__ bk,
    const float* __restrict__ Wq, const float* __restrict__ bq,
    const float* __restrict__ Wv, const float* __restrict__ bv,
    const float* __restrict__ Ws, const float* __restrict__ bs,
    float* __restrict__ OutS)
{
    __shared__ float Xs[64][36];
    __shared__ float Wsh[32][128];

    const int sel = blockIdx.y;
    const float* W   = (sel == 0) ? Wk : (sel == 1) ? Wq : (sel == 2) ? Wv : Ws;
    const float* bia = (sel == 0) ? bk : (sel == 1) ? bq : (sel == 2) ? bv : bs;

    const int tid = threadIdx.x;
    const int tx = tid & 15, ty = tid >> 4;
    const int rowBase = blockIdx.x * 64;

    u64 acc[4][4];
#pragma unroll
    for (int i = 0; i < 4; i++)
#pragma unroll
        for (int j = 0; j < 4; j++) acc[i][j] = 0ull;

    for (int kc = 0; kc < NC; kc += 32) {
#pragma unroll
        for (int u = 0; u < 2; u++) {
            int idx = tid + u * 256;
            int r = idx >> 3, c4 = idx & 7;
            float4 v = *(const float4*)(X + (size_t)(rowBase + r) * NC + kc + c4 * 4);
            *(float4*)(&Xs[r][c4 * 4]) = v;
        }
#pragma unroll
        for (int u = 0; u < 4; u++) {
            int idx = tid + u * 256;
            int r = idx >> 5, c4 = idx & 31;
            float4 v = *(const float4*)(W + (size_t)(kc + r) * NCP + c4 * 4);
            *(float4*)(&Wsh[r][c4 * 4]) = v;
        }
        __syncthreads();
#pragma unroll
        for (int kk = 0; kk < 32; kk++) {
            u64 w2[4];
#pragma unroll
            for (int j = 0; j < 4; j++)
                w2[j] = *(const u64*)(&Wsh[kk][2 * (tx + 16 * j)]);
#pragma unroll
            for (int i = 0; i < 4; i++) {
                float xv = Xs[ty * 4 + i][kk];
                u64 x2 = pack2(xv, xv);
#pragma unroll
                for (int j = 0; j < 4; j++)
                    acc[i][j] = ffma2(x2, w2[j], acc[i][j]);
            }
        }
        __syncthreads();
    }

    __nv_bfloat16* Yh = (sel == 0) ? g_Khi : g_Qhi;
    __nv_bfloat16* Yl = (sel == 0) ? g_Klo : g_Qlo;
    float*         Yf = (sel == 2) ? g_V   : OutS;

#pragma unroll
    for (int j = 0; j < 4; j++) {
        int p = tx + 16 * j;
        float2 bb = *(const float2*)(bia + 2 * p);
#pragma unroll
        for (int i = 0; i < 4; i++) {
            float2 v = unpack2(acc[i][j]);
            v.x += bb.x; v.y += bb.y;
            size_t off = (size_t)(rowBase + ty * 4 + i) * NCP + 2 * p;
            if (sel <= 1) {
                __nv_bfloat16 h0, l0, h1, l1;
                bsplit(v.x, h0, l0); bsplit(v.y, h1, l1);
                *(uint32_t*)(Yh + off) = pk(h0, h1);
                *(uint32_t*)(Yl + off) = pk(l0, l1);
            } else {
                *(float2*)(Yf + off) = v;
            }
        }
    }
}

// ============================================================================
// Kernel 2: V -> V^T with bf16 split  ([b][n][c] f32 -> [b][c][n] hi/lo bf16).
// ============================================================================
__global__ void vt_kernel()
{
    __shared__ float t[32][33];
    const int b  = blockIdx.z;
    const int n0 = blockIdx.x * 32;
    const int c0 = blockIdx.y * 32;
    const int tx = threadIdx.x, ty = threadIdx.y;   // 32 x 8
#pragma unroll
    for (int u = 0; u < 4; u++)
        t[ty * 4 + u][tx] = g_V[((size_t)b * NN + n0 + ty * 4 + u) * NCP + c0 + tx];
    __syncthreads();
#pragma unroll
    for (int u = 0; u < 4; u++) {
        float x = t[tx][ty * 4 + u];                // = V[n0+tx][c0+ty*4+u]
        __nv_bfloat16 h, l; bsplit(x, h, l);
        size_t off = ((size_t)b * NCP + c0 + ty * 4 + u) * NN + n0 + tx;
        g_Vthi[off] = h;
        g_Vtlo[off] = l;
    }
}

// ============================================================================
// Kernel 3: scores S = K @ Q^T, bf16 mma.sync, 3-product split.
//   CTA 128m x 128n, k=128 in 2 panels of 64. 8 warps: 2(m) x 4(n),
//   warp tile 64x32 -> 4 m16-tiles x 4 n8-tiles. Per k16: 48 LDS / 48 mma.
// ============================================================================
#define SC_SMEM (4 * 128 * SKS * 2)   // 73728 B: Ahi, Alo, Bhi, Blo

__global__ void __launch_bounds__(256) scores_kernel()
{
    extern __shared__ __align__(16) char smraw[];
    __nv_bfloat16* sAh = (__nv_bfloat16*)smraw;
    __nv_bfloat16* sAl = sAh + 128 * SKS;
    __nv_bfloat16* sBh = sAl + 128 * SKS;
    __nv_bfloat16* sBl = sBh + 128 * SKS;

    const int tid = threadIdx.x;
    const int lane = tid & 31, w = tid >> 5;
    const int g = lane >> 2, q4 = lane & 3;
    const int wm = w & 1, wn = w >> 1;              // 2 x 4 warp grid
    const int nt = blockIdx.x, mt = blockIdx.y, b = blockIdx.z;

    const __nv_bfloat16* Ahg = g_Khi + (size_t)(b * NN + mt * 128) * NCP;
    const __nv_bfloat16* Alg = g_Klo + (size_t)(b * NN + mt * 128) * NCP;
    const __nv_bfloat16* Bhg = g_Qhi + (size_t)(b * NN + nt * 128) * NCP;
    const __nv_bfloat16* Blg = g_Qlo + (size_t)(b * NN + nt * 128) * NCP;

    float C[4][4][4];
#pragma unroll
    for (int mi = 0; mi < 4; mi++)
#pragma unroll
        for (int ni = 0; ni < 4; ni++)
#pragma unroll
            for (int e = 0; e < 4; e++) C[mi][ni][e] = 0.f;

    for (int kp = 0; kp < 2; kp++) {
        __syncthreads();
        // fill 4 buffers: 128 rows x 64 bf16 each; 4 float4 per thread per buffer
#pragma unroll
        for (int u = 0; u < 4; u++) {
            int idx = tid + u * 256;
            int r = idx >> 3, c8 = idx & 7;
            size_t go = (size_t)r * NCP + kp * 64 + c8 * 8;
            int so = r * SKS + c8 * 8;
            *(float4*)(sAh + so) = *(const float4*)(Ahg + go);
            *(float4*)(sAl + so) = *(const float4*)(Alg + go);
            *(float4*)(sBh + so) = *(const float4*)(Bhg + go);
            *(float4*)(sBl + so) = *(const float4*)(Blg + go);
        }
        __syncthreads();

#pragma unroll
        for (int kc = 0; kc < 4; kc++) {
            const int k0 = kc * 16 + q4 * 2;
            uint32_t Bh[4][2], Bl[4][2];
#pragma unroll
            for (int ni = 0; ni < 4; ni++) {
                int col = wn * 32 + ni * 8 + g;
                Bh[ni][0] = *(const uint32_t*)(sBh + col * SKS + k0);
                Bh[ni][1] = *(const uint32_t*)(sBh + col * SKS + k0 + 8);
                Bl[ni][0] = *(const uint32_t*)(sBl + col * SKS + k0);
                Bl[ni][1] = *(const uint32_t*)(sBl + col * SKS + k0 + 8);
            }
#pragma unroll
            for (int mi = 0; mi < 4; mi++) {
                int row = wm * 64 + mi * 16 + g;
                uint32_t a0 = *(const uint32_t*)(sAh + row * SKS + k0);
                uint32_t a1 = *(const uint32_t*)(sAh + (row + 8) * SKS + k0);
                uint32_t a2 = *(const uint32_t*)(sAh + row * SKS + k0 + 8);
                uint32_t a3 = *(const uint32_t*)(sAh + (row + 8) * SKS + k0 + 8);
                uint32_t l0 = *(const uint32_t*)(sAl + row * SKS + k0);
                uint32_t l1 = *(const uint32_t*)(sAl + (row + 8) * SKS + k0);
                uint32_t l2 = *(const uint32_t*)(sAl + row * SKS + k0 + 8);
                uint32_t l3 = *(const uint32_t*)(sAl + (row + 8) * SKS + k0 + 8);
#pragma unroll
                for (int ni = 0; ni < 4; ni++) {
                    mma_bf16(C[mi][ni], a0, a1, a2, a3, Bh[ni][0], Bh[ni][1]); // hh
                    mma_bf16(C[mi][ni], a0, a1, a2, a3, Bl[ni][0], Bl[ni][1]); // hl
                    mma_bf16(C[mi][ni], l0, l1, l2, l3, Bh[ni][0], Bh[ni][1]); // lh
                }
            }
        }
    }

    // epilogue: scatter C frags to g_S
#pragma unroll
    for (int mi = 0; mi < 4; mi++) {
#pragma unroll
        for (int ni = 0; ni < 4; ni++) {
            int row = mt * 128 + wm * 64 + mi * 16 + g;
            int col = nt * 128 + wn * 32 + ni * 8 + q4 * 2;
            float* p0 = g_S + ((size_t)(b * NN + row)) * NN + col;
            float* p1 = g_S + ((size_t)(b * NN + row + 8)) * NN + col;
            *(float2*)p0 = make_float2(C[mi][ni][0], C[mi][ni][1]);
            *(float2*)p1 = make_float2(C[mi][ni][2], C[mi][ni][3]);
        }
    }
}

// ============================================================================
// Kernel 4: per-row softmax stats (m, 1/l). One warp per row.
// ============================================================================
__global__ void stats_kernel()
{
    const int warp = (blockIdx.x * blockDim.x + threadIdx.x) >> 5;
    const int lane = threadIdx.x & 31;
    if (warp >= NB * NN) return;
    const float* row = g_S + (size_t)warp * NN;

    float m = -1e30f, l = 0.f;
#pragma unroll 4
    for (int i = 0; i < NN / 128; i++) {
        float4 v = *(const float4*)(row + i * 128 + lane * 4);
        float m4 = fmaxf(fmaxf(v.x, v.y), fmaxf(v.z, v.w));
        float mn = fmaxf(m, m4);
        l = l * __expf(m - mn) + __expf(v.x - mn) + __expf(v.y - mn)
                               + __expf(v.z - mn) + __expf(v.w - mn);
        m = mn;
    }
#pragma unroll
    for (int off = 16; off; off >>= 1) {
        float mo = __shfl_xor_sync(0xffffffffu, m, off);
        float lo = __shfl_xor_sync(0xffffffffu, l, off);
        float mn = fmaxf(m, mo);
        l = l * __expf(m - mn) + lo * __expf(mo - mn);
        m = mn;
    }
    if (lane == 0) { g_Ms[warp] = m; g_Li[warp] = 1.0f / l; }
}

// ============================================================================
// Kernel 5: O = P @ V + shortcut, bf16 mma.sync, 3-product split.
//   CTA 64m x 128c, k(n)=4096 in 64 chunks of 64. 8 warps: 2(m) x 4(c),
//   warp tile 32m x 32c. exp((s-m))*invl + bf16 split fused into P-tile fill.
//   grid 256 CTAs -> 2/SM (smem 55.3 KB), fully resident.
// ============================================================================
#define PV_SMEM ((2 * 64 + 2 * 128) * SKS * 2)   // 55296 B

__global__ void __launch_bounds__(256) pv_kernel(float* __restrict__ Out)
{
    extern __shared__ __align__(16) char smraw[];
    __nv_bfloat16* sPh = (__nv_bfloat16*)smraw;      // [64][SKS]
    __nv_bfloat16* sPl = sPh + 64 * SKS;
    __nv_bfloat16* sVh = sPl + 64 * SKS;             // [128][SKS]
    __nv_bfloat16* sVl = sVh + 128 * SKS;

    const int tid = threadIdx.x;
    const int lane = tid & 31, w = tid >> 5;
    const int g = lane >> 2, q4 = lane & 3;
    const int wm = w & 1, wc = w >> 1;               // 2(m) x 4(c)
    const int mt = blockIdx.x, b = blockIdx.y;

    float C[2][4][4];
#pragma unroll
    for (int mi = 0; mi < 2; mi++)
#pragma unroll
        for (int ci = 0; ci < 4; ci++)
#pragma unroll
            for (int e = 0; e < 4; e++) C[mi][ci][e] = 0.f;

    // S-fill assignment: 4 float4 of one quarter-row region per thread
    int sr[4]; float mr[4], il[4];
    const float* Srp[4];
#pragma unroll
    for (int u = 0; u < 4; u++) {
        int idx = tid + u * 256;
        sr[u] = idx >> 4;                             // S row 0..63
        int rowg = b * NN + mt * 64 + sr[u];
        mr[u] = g_Ms[rowg];
        il[u] = g_Li[rowg];
        Srp[u] = g_S + (size_t)rowg * NN;
    }

    for (int ch = 0; ch < NN / 64; ch++) {
        __syncthreads();
        // P tile: load S chunk, softmax-normalize, bf16-split, store
#pragma unroll
        for (int u = 0; u < 4; u++) {
            int q = (tid + u * 256) & 15;
            float4 s = *(const float4*)(Srp[u] + ch * 64 + q * 4);
            float px = __expf(s.x - mr[u]) * il[u];
            float py = __expf(s.y - mr[u]) * il[u];
            float pz = __expf(s.z - mr[u]) * il[u];
            float pw = __expf(s.w - mr[u]) * il[u];
            __nv_bfloat16 h0,l0,h1,l1,h2,l2,h3,l3;
            bsplit(px,h0,l0); bsplit(py,h1,l1); bsplit(pz,h2,l2); bsplit(pw,h3,l3);
            int so = sr[u] * SKS + q * 4;
            *(uint2*)(sPh + so) = make_uint2(pk(h0,h1), pk(h2,h3));
            *(uint2*)(sPl + so) = make_uint2(pk(l0,l1), pk(l2,l3));
        }
        // V tile: 128 c-rows x 64 n
#pragma unroll
        for (int u = 0; u < 4; u++) {
            int idx = tid + u * 256;
            int r = idx >> 3, c8 = idx & 7;
            size_t go = ((size_t)(b * NCP + r)) * NN + ch * 64 + c8 * 8;
            int so = r * SKS + c8 * 8;
            *(float4*)(sVh + so) = *(const float4*)(g_Vthi + go);
            *(float4*)(sVl + so) = *(const float4*)(g_Vtlo + go);
        }
        __syncthreads();

#pragma unroll
        for (int kc = 0; kc < 4; kc++) {
            const int k0 = kc * 16 + q4 * 2;
            uint32_t Bh[4][2], Bl[4][2];
#pragma unroll
            for (int ci = 0; ci < 4; ci++) {
                int col = wc * 32 + ci * 8 + g;
                Bh[ci][0] = *(const uint32_t*)(sVh + col * SKS + k0);
                Bh[ci][1] = *(const uint32_t*)(sVh + col * SKS + k0 + 8);
                Bl[ci][0] = *(const uint32_t*)(sVl + col * SKS + k0);
                Bl[ci][1] = *(const uint32_t*)(sVl + col * SKS + k0 + 8);
            }
#pragma unroll
            for (int mi = 0; mi < 2; mi++) {
                int row = wm * 32 + mi * 16 + g;
                uint32_t a0 = *(const uint32_t*)(sPh + row * SKS + k0);
                uint32_t a1 = *(const uint32_t*)(sPh + (row + 8) * SKS + k0);
                uint32_t a2 = *(const uint32_t*)(sPh + row * SKS + k0 + 8);
                uint32_t a3 = *(const uint32_t*)(sPh + (row + 8) * SKS + k0 + 8);
                uint32_t l0 = *(const uint32_t*)(sPl + row * SKS + k0);
                uint32_t l1 = *(const uint32_t*)(sPl + (row + 8) * SKS + k0);
                uint32_t l2 = *(const uint32_t*)(sPl + row * SKS + k0 + 8);
                uint32_t l3 = *(const uint32_t*)(sPl + (row + 8) * SKS + k0 + 8);
#pragma unroll
                for (int ci = 0; ci < 4; ci++) {
                    mma_bf16(C[mi][ci], a0, a1, a2, a3, Bh[ci][0], Bh[ci][1]);
                    mma_bf16(C[mi][ci], a0, a1, a2, a3, Bl[ci][0], Bl[ci][1]);
                    mma_bf16(C[mi][ci], l0, l1, l2, l3, Bh[ci][0], Bh[ci][1]);
                }
            }
        }
    }

    // epilogue: Out += O (Out holds shortcut)
#pragma unroll
    for (int mi = 0; mi < 2; mi++) {
#pragma unroll
        for (int ci = 0; ci < 4; ci++) {
            int row = mt * 64 + wm * 32 + mi * 16 + g;
            int col = wc * 32 + ci * 8 + q4 * 2;
            float* p0 = Out + ((size_t)(b * NN + row)) * NCP + col;
            float* p1 = Out + ((size_t)(b * NN + row + 8)) * NCP + col;
            float2 s0 = *(float2*)p0, s1 = *(float2*)p1;
            *(float2*)p0 = make_float2(C[mi][ci][0] + s0.x, C[mi][ci][1] + s0.y);
            *(float2*)p1 = make_float2(C[mi][ci][2] + s1.x, C[mi][ci][3] + s1.y);
        }
    }
}

// ============================================================================
// Launch
// ============================================================================
extern "C" void kernel_launch(void* const* d_in, const int* in_sizes, int n_in,
                              void* d_out, int out_size) {
    (void)in_sizes; (void)n_in; (void)out_size;
    const float* x  = (const float*)d_in[0];
    const float* Wk = (const float*)d_in[1];
    const float* bk = (const float*)d_in[2];
    const float* Wq = (const float*)d_in[3];
    const float* bq = (const float*)d_in[4];
    const float* Wv = (const float*)d_in[5];
    const float* bv = (const float*)d_in[6];
    const float* Ws = (const float*)d_in[7];
    const float* bs = (const float*)d_in[8];
    float* out = (float*)d_out;

    cudaFuncSetAttribute(scores_kernel, cudaFuncAttributeMaxDynamicSharedMemorySize, SC_SMEM);
    cudaFuncSetAttribute(pv_kernel,     cudaFuncAttributeMaxDynamicSharedMemorySize, PV_SMEM);

    // 1) projections: K,Q -> bf16 hi/lo; V -> f32; shortcut -> d_out
    proj_kernel<<<dim3(NB * NN / 64, 4), 256>>>(x, Wk, bk, Wq, bq, Wv, bv, Ws, bs, out);
    // 2) V -> V^T bf16 hi/lo
    vt_kernel<<<dim3(NN / 32, NCP / 32, NB), dim3(32, 8)>>>();
    // 3) scores S = K @ Q^T (bf16 split, mma.sync)
    scores_kernel<<<dim3(NN / 128, NN / 128, NB), 256, SC_SMEM>>>();
    // 4) per-row softmax stats
    stats_kernel<<<(NB * NN) / 8, 256>>>();
    // 5) O = P @ V (bf16 split) + shortcut
    pv_kernel<<<dim3(NN / 64, NB), 256, PV_SMEM>>>(out);
}

// round 11
// speedup vs baseline: 3.0549x; 1.0517x over previous
#include <cuda_runtime.h>
#include <cuda_bf16.h>
#include <cstdint>

// Problem constants
#define NB  4
#define NN  4096   // H*W
#define NC  256
#define NCP 128

// Scratch (static __device__ arrays: the sanctioned no-alloc scratch mechanism).
static __device__ float          g_V  [NB * NN * NCP];       // fp32 V
static __device__ __nv_bfloat16  g_Khi[NB * NN * NCP];       // K split hi/lo  [b*NN+n][c]
static __device__ __nv_bfloat16  g_Klo[NB * NN * NCP];
static __device__ __nv_bfloat16  g_Qhi[NB * NN * NCP];       // Q split hi/lo
static __device__ __nv_bfloat16  g_Qlo[NB * NN * NCP];
static __device__ __nv_bfloat16  g_Vthi[NB * NCP * NN];      // V^T hi/lo  [b*NCP+c][n]
static __device__ __nv_bfloat16  g_Vtlo[NB * NCP * NN];
static __device__ float          g_S [NB * NN * NN];         // scores (256 MB)
static __device__ unsigned       g_MsEnc[NB * NN];           // row max (order-encoded uint)
static __device__ __nv_bfloat16  g_Wth[4 * NCP * NC];        // W^T splits [sel][col][k]
static __device__ __nv_bfloat16  g_Wtl[4 * NCP * NC];

// ---- bf16 split + pack helpers ----
__device__ __forceinline__ void bsplit(float x, __nv_bfloat16& h, __nv_bfloat16& l) {
    h = __float2bfloat16(x);
    l = __float2bfloat16(x - __bfloat162float(h));
}
__device__ __forceinline__ uint32_t pk(__nv_bfloat16 a, __nv_bfloat16 b) {
    return (uint32_t)__bfloat16_as_ushort(a) | ((uint32_t)__bfloat16_as_ushort(b) << 16);
}

// ---- order-preserving float <-> uint encoding (for atomicMax row-max) ----
__device__ __forceinline__ unsigned encf(float f) {
    unsigned u = __float_as_uint(f);
    return (u & 0x80000000u) ? ~u : (u | 0x80000000u);
}
__device__ __forceinline__ float decf(unsigned e) {
    unsigned u = (e & 0x80000000u) ? (e ^ 0x80000000u) : ~e;
    return __uint_as_float(u);
}

// ---- warp MMA: m16n8k16, row.col, bf16 in, fp32 acc (baseline PTX, sm_80+) ----
__device__ __forceinline__ void mma_bf16(float c[4], uint32_t a0, uint32_t a1,
                                         uint32_t a2, uint32_t a3,
                                         uint32_t b0, uint32_t b1) {
    asm volatile("mma.sync.aligned.m16n8k16.row.col.f32.bf16.bf16.f32 "
        "{%0,%1,%2,%3}, {%4,%5,%6,%7}, {%8,%9}, {%0,%1,%2,%3};"
        : "+f"(c[0]), "+f"(c[1]), "+f"(c[2]), "+f"(c[3])
        : "r"(a0), "r"(a1), "r"(a2), "r"(a3), "r"(b0), "r"(b1));
}

#define SKS 72   // smem tile stride in bf16 elems (conflict-free fragment LDS)

// ============================================================================
// Kernel 0a: pre-split + transpose weights: W[k][c] f32 -> [sel][c][k] bf16 hi/lo.
// ============================================================================
__global__ void wsplit_kernel(const float* __restrict__ Wk, const float* __restrict__ Wq,
                              const float* __restrict__ Wv, const float* __restrict__ Ws)
{
    const int sel = blockIdx.x;
    const float* W = (sel == 0) ? Wk : (sel == 1) ? Wq : (sel == 2) ? Wv : Ws;
    for (int idx = threadIdx.x; idx < NCP * NC; idx += blockDim.x) {
        int c = idx >> 8, k = idx & 255;
        __nv_bfloat16 h, l; bsplit(W[(size_t)k * NCP + c], h, l);
        g_Wth[sel * NCP * NC + idx] = h;
        g_Wtl[sel * NCP * NC + idx] = l;
    }
}

// Kernel 0b: reset row-max accumulators to an encoded -inf-like sentinel.
__global__ void init_ms_kernel()
{
    int i = blockIdx.x * blockDim.x + threadIdx.x;
    if (i < NB * NN) g_MsEnc[i] = encf(-3e38f);
}

// ============================================================================
// Kernel 1: projections via bf16 mma 3-product split.
//   CTA 128 rows x 128 cols, k=256 in 4 panels of 64. 8 warps 2(m) x 4(n).
//   sel 0/1 -> K/Q bf16 hi/lo; sel 2 -> V f32; sel 3 -> shortcut -> Out f32.
// ============================================================================
#define PRJ_SMEM (4 * 128 * SKS * 2)   // 73728 B

__global__ void __launch_bounds__(256) proj_kernel(
    const float* __restrict__ X,
    const float* __restrict__ bk, const float* __restrict__ bq,
    const float* __restrict__ bv, const float* __restrict__ bs,
    float* __restrict__ OutS)
{
    extern __shared__ __align__(16) char smraw[];
    __nv_bfloat16* sXh = (__nv_bfloat16*)smraw;
    __nv_bfloat16* sXl = sXh + 128 * SKS;
    __nv_bfloat16* sWh = sXl + 128 * SKS;
    __nv_bfloat16* sWl = sWh + 128 * SKS;

    const int sel = blockIdx.y;
    const float* bia = (sel == 0) ? bk : (sel == 1) ? bq : (sel == 2) ? bv : bs;
    const __nv_bfloat16* Wh = g_Wth + sel * NCP * NC;
    const __nv_bfloat16* Wl = g_Wtl + sel * NCP * NC;

    const int tid = threadIdx.x;
    const int lane = tid & 31, w = tid >> 5;
    const int g = lane >> 2, q4 = lane & 3;
    const int wm = w & 1, wn = w >> 1;
    const int rowBase = blockIdx.x * 128;

    float C[4][4][4];
#pragma unroll
    for (int mi = 0; mi < 4; mi++)
#pragma unroll
        for (int ni = 0; ni < 4; ni++)
#pragma unroll
            for (int e = 0; e < 4; e++) C[mi][ni][e] = 0.f;

    for (int kp = 0; kp < 4; kp++) {
        __syncthreads();
        // X panel: 128 rows x 64 k, split on the fly
#pragma unroll
        for (int u = 0; u < 8; u++) {
            int idx = tid + u * 256;
            int r = idx >> 4, c4 = idx & 15;
            float4 v = *(const float4*)(X + (size_t)(rowBase + r) * NC + kp * 64 + c4 * 4);
            __nv_bfloat16 h0,l0,h1,l1,h2,l2,h3,l3;
            bsplit(v.x,h0,l0); bsplit(v.y,h1,l1); bsplit(v.z,h2,l2); bsplit(v.w,h3,l3);
            int so = r * SKS + c4 * 4;
            *(uint2*)(sXh + so) = make_uint2(pk(h0,h1), pk(h2,h3));
            *(uint2*)(sXl + so) = make_uint2(pk(l0,l1), pk(l2,l3));
        }
        // W panel: 128 cols x 64 k, pre-split bf16, k-contiguous
#pragma unroll
        for (int u = 0; u < 4; u++) {
            int idx = tid + u * 256;
            int col = idx >> 3, k8 = idx & 7;
            int go = col * NC + kp * 64 + k8 * 8;
            int so = col * SKS + k8 * 8;
            *(uint4*)(sWh + so) = *(const uint4*)(Wh + go);
            *(uint4*)(sWl + so) = *(const uint4*)(Wl + go);
        }
        __syncthreads();

#pragma unroll
        for (int kc = 0; kc < 4; kc++) {
            const int k0 = kc * 16 + q4 * 2;
            uint32_t Bh[4][2], Bl[4][2];
#pragma unroll
            for (int ni = 0; ni < 4; ni++) {
                int col = wn * 32 + ni * 8 + g;
                Bh[ni][0] = *(const uint32_t*)(sWh + col * SKS + k0);
                Bh[ni][1] = *(const uint32_t*)(sWh + col * SKS + k0 + 8);
                Bl[ni][0] = *(const uint32_t*)(sWl + col * SKS + k0);
                Bl[ni][1] = *(const uint32_t*)(sWl + col * SKS + k0 + 8);
            }
#pragma unroll
            for (int mi = 0; mi < 4; mi++) {
                int row = wm * 64 + mi * 16 + g;
                uint32_t a0 = *(const uint32_t*)(sXh + row * SKS + k0);
                uint32_t a1 = *(const uint32_t*)(sXh + (row + 8) * SKS + k0);
                uint32_t a2 = *(const uint32_t*)(sXh + row * SKS + k0 + 8);
                uint32_t a3 = *(const uint32_t*)(sXh + (row + 8) * SKS + k0 + 8);
                uint32_t l0 = *(const uint32_t*)(sXl + row * SKS + k0);
                uint32_t l1 = *(const uint32_t*)(sXl + (row + 8) * SKS + k0);
                uint32_t l2 = *(const uint32_t*)(sXl + row * SKS + k0 + 8);
                uint32_t l3 = *(const uint32_t*)(sXl + (row + 8) * SKS + k0 + 8);
#pragma unroll
                for (int ni = 0; ni < 4; ni++) {
                    mma_bf16(C[mi][ni], a0, a1, a2, a3, Bh[ni][0], Bh[ni][1]); // hh
                    mma_bf16(C[mi][ni], a0, a1, a2, a3, Bl[ni][0], Bl[ni][1]); // hl
                    mma_bf16(C[mi][ni], l0, l1, l2, l3, Bh[ni][0], Bh[ni][1]); // lh
                }
            }
        }
    }

    // epilogue: bias + dispatch per sel
#pragma unroll
    for (int ni = 0; ni < 4; ni++) {
        int col = wn * 32 + ni * 8 + q4 * 2;
        float2 bb = *(const float2*)(bia + col);
#pragma unroll
        for (int mi = 0; mi < 4; mi++) {
            int row = rowBase + wm * 64 + mi * 16 + g;
            float v0 = C[mi][ni][0] + bb.x, v1 = C[mi][ni][1] + bb.y;
            float v2 = C[mi][ni][2] + bb.x, v3 = C[mi][ni][3] + bb.y;
            size_t o0 = (size_t)row * NCP + col;
            size_t o1 = (size_t)(row + 8) * NCP + col;
            if (sel <= 1) {
                __nv_bfloat16* Yh = (sel == 0) ? g_Khi : g_Qhi;
                __nv_bfloat16* Yl = (sel == 0) ? g_Klo : g_Qlo;
                __nv_bfloat16 h0,l0,h1,l1;
                bsplit(v0,h0,l0); bsplit(v1,h1,l1);
                *(uint32_t*)(Yh + o0) = pk(h0,h1);
                *(uint32_t*)(Yl + o0) = pk(l0,l1);
                bsplit(v2,h0,l0); bsplit(v3,h1,l1);
                *(uint32_t*)(Yh + o1) = pk(h0,h1);
                *(uint32_t*)(Yl + o1) = pk(l0,l1);
            } else {
                float* Yf = (sel == 2) ? g_V : OutS;
                *(float2*)(Yf + o0) = make_float2(v0, v1);
                *(float2*)(Yf + o1) = make_float2(v2, v3);
            }
        }
    }
}

// ============================================================================
// Kernel 2: V -> V^T bf16 hi/lo  ([b][n][c] f32 -> [b][c][n]).
// ============================================================================
__global__ void vt_kernel()
{
    __shared__ float t[32][33];
    const int b  = blockIdx.z;
    const int n0 = blockIdx.x * 32;
    const int c0 = blockIdx.y * 32;
    const int tx = threadIdx.x, ty = threadIdx.y;   // 32 x 8
#pragma unroll
    for (int u = 0; u < 4; u++)
        t[ty * 4 + u][tx] = g_V[((size_t)b * NN + n0 + ty * 4 + u) * NCP + c0 + tx];
    __syncthreads();
#pragma unroll
    for (int u = 0; u < 4; u++) {
        float x = t[tx][ty * 4 + u];
        __nv_bfloat16 h, l; bsplit(x, h, l);
        size_t off = ((size_t)b * NCP + c0 + ty * 4 + u) * NN + n0 + tx;
        g_Vthi[off] = h;
        g_Vtlo[off] = l;
    }
}

// ============================================================================
// Kernel 3: scores S = K @ Q^T (3-product split) + row-max atomics.
// ============================================================================
#define SC_SMEM (4 * 128 * SKS * 2)   // 73728 B

__global__ void __launch_bounds__(256) scores_kernel()
{
    extern __shared__ __align__(16) char smraw[];
    __nv_bfloat16* sAh = (__nv_bfloat16*)smraw;
    __nv_bfloat16* sAl = sAh + 128 * SKS;
    __nv_bfloat16* sBh = sAl + 128 * SKS;
    __nv_bfloat16* sBl = sBh + 128 * SKS;

    const int tid = threadIdx.x;
    const int lane = tid & 31, w = tid >> 5;
    const int g = lane >> 2, q4 = lane & 3;
    const int wm = w & 1, wn = w >> 1;
    const int nt = blockIdx.x, mt = blockIdx.y, b = blockIdx.z;

    const __nv_bfloat16* Ahg = g_Khi + (size_t)(b * NN + mt * 128) * NCP;
    const __nv_bfloat16* Alg = g_Klo + (size_t)(b * NN + mt * 128) * NCP;
    const __nv_bfloat16* Bhg = g_Qhi + (size_t)(b * NN + nt * 128) * NCP;
    const __nv_bfloat16* Blg = g_Qlo + (size_t)(b * NN + nt * 128) * NCP;

    float C[4][4][4];
#pragma unroll
    for (int mi = 0; mi < 4; mi++)
#pragma unroll
        for (int ni = 0; ni < 4; ni++)
#pragma unroll
            for (int e = 0; e < 4; e++) C[mi][ni][e] = 0.f;

    for (int kp = 0; kp < 2; kp++) {
        __syncthreads();
#pragma unroll
        for (int u = 0; u < 4; u++) {
            int idx = tid + u * 256;
            int r = idx >> 3, c8 = idx & 7;
            size_t go = (size_t)r * NCP + kp * 64 + c8 * 8;
            int so = r * SKS + c8 * 8;
            *(float4*)(sAh + so) = *(const float4*)(Ahg + go);
            *(float4*)(sAl + so) = *(const float4*)(Alg + go);
            *(float4*)(sBh + so) = *(const float4*)(Bhg + go);
            *(float4*)(sBl + so) = *(const float4*)(Blg + go);
        }
        __syncthreads();

#pragma unroll
        for (int kc = 0; kc < 4; kc++) {
            const int k0 = kc * 16 + q4 * 2;
            uint32_t Bh[4][2], Bl[4][2];
#pragma unroll
            for (int ni = 0; ni < 4; ni++) {
                int col = wn * 32 + ni * 8 + g;
                Bh[ni][0] = *(const uint32_t*)(sBh + col * SKS + k0);
                Bh[ni][1] = *(const uint32_t*)(sBh + col * SKS + k0 + 8);
                Bl[ni][0] = *(const uint32_t*)(sBl + col * SKS + k0);
                Bl[ni][1] = *(const uint32_t*)(sBl + col * SKS + k0 + 8);
            }
#pragma unroll
            for (int mi = 0; mi < 4; mi++) {
                int row = wm * 64 + mi * 16 + g;
                uint32_t a0 = *(const uint32_t*)(sAh + row * SKS + k0);
                uint32_t a1 = *(const uint32_t*)(sAh + (row + 8) * SKS + k0);
                uint32_t a2 = *(const uint32_t*)(sAh + row * SKS + k0 + 8);
                uint32_t a3 = *(const uint32_t*)(sAh + (row + 8) * SKS + k0 + 8);
                uint32_t l0 = *(const uint32_t*)(sAl + row * SKS + k0);
                uint32_t l1 = *(const uint32_t*)(sAl + (row + 8) * SKS + k0);
                uint32_t l2 = *(const uint32_t*)(sAl + row * SKS + k0 + 8);
                uint32_t l3 = *(const uint32_t*)(sAl + (row + 8) * SKS + k0 + 8);
#pragma unroll
                for (int ni = 0; ni < 4; ni++) {
                    mma_bf16(C[mi][ni], a0, a1, a2, a3, Bh[ni][0], Bh[ni][1]); // hh
                    mma_bf16(C[mi][ni], a0, a1, a2, a3, Bl[ni][0], Bl[ni][1]); // hl
                    mma_bf16(C[mi][ni], l0, l1, l2, l3, Bh[ni][0], Bh[ni][1]); // lh
                }
            }
        }
    }

    // epilogue: write S + per-row max (fragment reduce + shfl over quad + atomicMax)
#pragma unroll
    for (int mi = 0; mi < 4; mi++) {
        float mx0 = -1e30f, mx1 = -1e30f;
#pragma unroll
        for (int ni = 0; ni < 4; ni++) {
            int row = mt * 128 + wm * 64 + mi * 16 + g;
            int col = nt * 128 + wn * 32 + ni * 8 + q4 * 2;
            float* p0 = g_S + ((size_t)(b * NN + row)) * NN + col;
            float* p1 = g_S + ((size_t)(b * NN + row + 8)) * NN + col;
            *(float2*)p0 = make_float2(C[mi][ni][0], C[mi][ni][1]);
            *(float2*)p1 = make_float2(C[mi][ni][2], C[mi][ni][3]);
            mx0 = fmaxf(mx0, fmaxf(C[mi][ni][0], C[mi][ni][1]));
            mx1 = fmaxf(mx1, fmaxf(C[mi][ni][2], C[mi][ni][3]));
        }
        mx0 = fmaxf(mx0, __shfl_xor_sync(0xffffffffu, mx0, 1));
        mx0 = fmaxf(mx0, __shfl_xor_sync(0xffffffffu, mx0, 2));
        mx1 = fmaxf(mx1, __shfl_xor_sync(0xffffffffu, mx1, 1));
        mx1 = fmaxf(mx1, __shfl_xor_sync(0xffffffffu, mx1, 2));
        if (q4 == 0) {
            int rg = b * NN + mt * 128 + wm * 64 + mi * 16 + g;
            atomicMax(&g_MsEnc[rg],     encf(mx0));
            atomicMax(&g_MsEnc[rg + 8], encf(mx1));
        }
    }
}

// ============================================================================
// Kernel 4: O = softmax(S) @ V + shortcut.  3-product split
//   (Ph*Vh + Pl*Vh + Ph*Vl — the Vl term is required: v_lo rms ~4e-3).
//   Unnormalized P = exp(s - rowmax); l accumulated in-kernel; 1/l in epilogue.
// ============================================================================
#define PV_SMEM ((2 * 64 + 2 * 128) * SKS * 2)   // 55296 B

__global__ void __launch_bounds__(256) pv_kernel(float* __restrict__ Out)
{
    extern __shared__ __align__(16) char smraw[];
    __nv_bfloat16* sPh = (__nv_bfloat16*)smraw;      // [64][SKS]
    __nv_bfloat16* sPl = sPh + 64 * SKS;
    __nv_bfloat16* sVh = sPl + 64 * SKS;             // [128][SKS]
    __nv_bfloat16* sVl = sVh + 128 * SKS;

    const int tid = threadIdx.x;
    const int lane = tid & 31, w = tid >> 5;
    const int g = lane >> 2, q4 = lane & 3;
    const int wm = w & 1, wc = w >> 1;
    const int mt = blockIdx.x, b = blockIdx.y;

    float C[2][4][4];
#pragma unroll
    for (int mi = 0; mi < 2; mi++)
#pragma unroll
        for (int ci = 0; ci < 4; ci++)
#pragma unroll
            for (int e = 0; e < 4; e++) C[mi][ci][e] = 0.f;

    int sr[4]; float mr[4], psum[4];
    const float* Srp[4];
#pragma unroll
    for (int u = 0; u < 4; u++) {
        int idx = tid + u * 256;
        sr[u] = idx >> 4;
        int rowg = b * NN + mt * 64 + sr[u];
        mr[u] = decf(g_MsEnc[rowg]);
        psum[u] = 0.f;
        Srp[u] = g_S + (size_t)rowg * NN;
    }
    const int q = tid & 15;

    for (int ch = 0; ch < NN / 64; ch++) {
        __syncthreads();
        // P tile: exp(s - m) unnormalized, split, accumulate l
#pragma unroll
        for (int u = 0; u < 4; u++) {
            float4 s = *(const float4*)(Srp[u] + ch * 64 + q * 4);
            float px = __expf(s.x - mr[u]);
            float py = __expf(s.y - mr[u]);
            float pz = __expf(s.z - mr[u]);
            float pw = __expf(s.w - mr[u]);
            psum[u] += (px + py) + (pz + pw);
            __nv_bfloat16 h0,l0,h1,l1,h2,l2,h3,l3;
            bsplit(px,h0,l0); bsplit(py,h1,l1); bsplit(pz,h2,l2); bsplit(pw,h3,l3);
            int so = sr[u] * SKS + q * 4;
            *(uint2*)(sPh + so) = make_uint2(pk(h0,h1), pk(h2,h3));
            *(uint2*)(sPl + so) = make_uint2(pk(l0,l1), pk(l2,l3));
        }
        // V tile (hi + lo): 128 c-rows x 64 n
#pragma unroll
        for (int u = 0; u < 4; u++) {
            int idx = tid + u * 256;
            int r = idx >> 3, c8 = idx & 7;
            size_t go = ((size_t)(b * NCP + r)) * NN + ch * 64 + c8 * 8;
            int so = r * SKS + c8 * 8;
            *(uint4*)(sVh + so) = *(const uint4*)(g_Vthi + go);
            *(uint4*)(sVl + so) = *(const uint4*)(g_Vtlo + go);
        }
        __syncthreads();

#pragma unroll
        for (int kc = 0; kc < 4; kc++) {
            const int k0 = kc * 16 + q4 * 2;
            uint32_t Bh[4][2], Bl[4][2];
#pragma unroll
            for (int ci = 0; ci < 4; ci++) {
                int col = wc * 32 + ci * 8 + g;
                Bh[ci][0] = *(const uint32_t*)(sVh + col * SKS + k0);
                Bh[ci][1] = *(const uint32_t*)(sVh + col * SKS + k0 + 8);
                Bl[ci][0] = *(const uint32_t*)(sVl + col * SKS + k0);
                Bl[ci][1] = *(const uint32_t*)(sVl + col * SKS + k0 + 8);
            }
#pragma unroll
            for (int mi = 0; mi < 2; mi++) {
                int row = wm * 32 + mi * 16 + g;
                uint32_t a0 = *(const uint32_t*)(sPh + row * SKS + k0);
                uint32_t a1 = *(const uint32_t*)(sPh + (row + 8) * SKS + k0);
                uint32_t a2 = *(const uint32_t*)(sPh + row * SKS + k0 + 8);
                uint32_t a3 = *(const uint32_t*)(sPh + (row + 8) * SKS + k0 + 8);
                uint32_t l0 = *(const uint32_t*)(sPl + row * SKS + k0);
                uint32_t l1 = *(const uint32_t*)(sPl + (row + 8) * SKS + k0);
                uint32_t l2 = *(const uint32_t*)(sPl + row * SKS + k0 + 8);
                uint32_t l3 = *(const uint32_t*)(sPl + (row + 8) * SKS + k0 + 8);
#pragma unroll
                for (int ci = 0; ci < 4; ci++) {
                    mma_bf16(C[mi][ci], a0, a1, a2, a3, Bh[ci][0], Bh[ci][1]); // Ph*Vh
                    mma_bf16(C[mi][ci], a0, a1, a2, a3, Bl[ci][0], Bl[ci][1]); // Ph*Vl
                    mma_bf16(C[mi][ci], l0, l1, l2, l3, Bh[ci][0], Bh[ci][1]); // Pl*Vh
                }
            }
        }
    }

    // reduce l per row (16 partials), compute 1/l
    __syncthreads();
    float* sred = (float*)smraw;              // 64 x 16 floats (aliases sPh)
    float* sInv = sred + 64 * 16;             // 64 floats
#pragma unroll
    for (int u = 0; u < 4; u++) sred[sr[u] * 16 + q] = psum[u];
    __syncthreads();
    if (tid < 64) {
        float l = 0.f;
#pragma unroll
        for (int j = 0; j < 16; j++) l += sred[tid * 16 + j];
        sInv[tid] = 1.0f / l;
    }
    __syncthreads();

    // epilogue: Out = C/l + shortcut (Out holds shortcut)
#pragma unroll
    for (int mi = 0; mi < 2; mi++) {
        int rl = wm * 32 + mi * 16 + g;
        float i0 = sInv[rl], i1 = sInv[rl + 8];
#pragma unroll
        for (int ci = 0; ci < 4; ci++) {
            int row = mt * 64 + rl;
            int col = wc * 32 + ci * 8 + q4 * 2;
            float* p0 = Out + ((size_t)(b * NN + row)) * NCP + col;
            float* p1 = Out + ((size_t)(b * NN + row + 8)) * NCP + col;
            float2 s0 = *(float2*)p0, s1 = *(float2*)p1;
            *(float2*)p0 = make_float2(C[mi][ci][0] * i0 + s0.x, C[mi][ci][1] * i0 + s0.y);
            *(float2*)p1 = make_float2(C[mi][ci][2] * i1 + s1.x, C[mi][ci][3] * i1 + s1.y);
        }
    }
}

// ============================================================================
// Launch
// ============================================================================
extern "C" void kernel_launch(void* const* d_in, const int* in_sizes, int n_in,
                              void* d_out, int out_size) {
    (void)in_sizes; (void)n_in; (void)out_size;
    const float* x  = (const float*)d_in[0];
    const float* Wk = (const float*)d_in[1];
    const float* bk = (const float*)d_in[2];
    const float* Wq = (const float*)d_in[3];
    const float* bq = (const float*)d_in[4];
    const float* Wv = (const float*)d_in[5];
    const float* bv = (const float*)d_in[6];
    const float* Ws = (const float*)d_in[7];
    const float* bs = (const float*)d_in[8];
    float* out = (float*)d_out;

    cudaFuncSetAttribute(proj_kernel,   cudaFuncAttributeMaxDynamicSharedMemorySize, PRJ_SMEM);
    cudaFuncSetAttribute(scores_kernel, cudaFuncAttributeMaxDynamicSharedMemorySize, SC_SMEM);
    cudaFuncSetAttribute(pv_kernel,     cudaFuncAttributeMaxDynamicSharedMemorySize, PV_SMEM);

    // 0) weight pre-split + row-max reset
    wsplit_kernel<<<4, 256>>>(Wk, Wq, Wv, Ws);
    init_ms_kernel<<<(NB * NN + 255) / 256, 256>>>();
    // 1) projections (bf16 mma): K/Q hi-lo, V f32, shortcut -> d_out
    proj_kernel<<<dim3(NB * NN / 128, 4), 256, PRJ_SMEM>>>(x, bk, bq, bv, bs, out);
    // 2) V -> V^T bf16 hi/lo
    vt_kernel<<<dim3(NN / 32, NCP / 32, NB), dim3(32, 8)>>>();
    // 3) scores S = K @ Q^T + row-max atomics
    scores_kernel<<<dim3(NN / 128, NN / 128, NB), 256, SC_SMEM>>>();
    // 4) O = P @ V (3-product) + shortcut, l folded in
    pv_kernel<<<dim3(NN / 64, NB), 256, PV_SMEM>>>(out);
}

// round 12
// speedup vs baseline: 3.1183x; 1.0207x over previous
#include <cuda_runtime.h>
#include <cuda_bf16.h>
#include <cstdint>

// Problem constants
#define NB  4
#define NN  4096   // H*W
#define NC  256
#define NCP 128

// Scratch (static __device__ arrays: the sanctioned no-alloc scratch mechanism).
static __device__ float          g_V  [NB * NN * NCP];       // fp32 V
static __device__ __nv_bfloat16  g_Khi[NB * NN * NCP];       // K split hi/lo  [b*NN+n][c]
static __device__ __nv_bfloat16  g_Klo[NB * NN * NCP];
static __device__ __nv_bfloat16  g_Qhi[NB * NN * NCP];       // Q split hi/lo
static __device__ __nv_bfloat16  g_Qlo[NB * NN * NCP];
static __device__ __nv_bfloat16  g_Vthi[NB * NCP * NN];      // V^T hi/lo  [b*NCP+c][n]
static __device__ __nv_bfloat16  g_Vtlo[NB * NCP * NN];
static __device__ __nv_bfloat16  g_Wth[4 * NCP * NC];        // W^T splits [sel][col][k]
static __device__ __nv_bfloat16  g_Wtl[4 * NCP * NC];

// ---- bf16 split + pack helpers ----
__device__ __forceinline__ void bsplit(float x, __nv_bfloat16& h, __nv_bfloat16& l) {
    h = __float2bfloat16(x);
    l = __float2bfloat16(x - __bfloat162float(h));
}
__device__ __forceinline__ uint32_t pk(__nv_bfloat16 a, __nv_bfloat16 b) {
    return (uint32_t)__bfloat16_as_ushort(a) | ((uint32_t)__bfloat16_as_ushort(b) << 16);
}
// pack hi parts / lo parts of two floats
__device__ __forceinline__ uint32_t pkhi(float a, float b) {
    return pk(__float2bfloat16(a), __float2bfloat16(b));
}
__device__ __forceinline__ uint32_t pklo(float a, float b) {
    __nv_bfloat16 ha = __float2bfloat16(a), hb = __float2bfloat16(b);
    return pk(__float2bfloat16(a - __bfloat162float(ha)),
              __float2bfloat16(b - __bfloat162float(hb)));
}

// ---- warp MMA: m16n8k16, row.col, bf16 in, fp32 acc (baseline PTX, sm_80+) ----
__device__ __forceinline__ void mma_bf16(float c[4], uint32_t a0, uint32_t a1,
                                         uint32_t a2, uint32_t a3,
                                         uint32_t b0, uint32_t b1) {
    asm volatile("mma.sync.aligned.m16n8k16.row.col.f32.bf16.bf16.f32 "
        "{%0,%1,%2,%3}, {%4,%5,%6,%7}, {%8,%9}, {%0,%1,%2,%3};"
        : "+f"(c[0]), "+f"(c[1]), "+f"(c[2]), "+f"(c[3])
        : "r"(a0), "r"(a1), "r"(a2), "r"(a3), "r"(b0), "r"(b1));
}

#define SKS 72   // 64-wide tile stride (bf16 elems): row step 144B = 4 banks -> conflict-free
#define KS2 136  // 128-wide tile stride: row step 272B = 4 banks -> conflict-free

// ============================================================================
// Kernel 0: pre-split + transpose weights: W[k][c] f32 -> [sel][c][k] bf16 hi/lo.
// ============================================================================
__global__ void wsplit_kernel(const float* __restrict__ Wk, const float* __restrict__ Wq,
                              const float* __restrict__ Wv, const float* __restrict__ Ws)
{
    const int sel = blockIdx.x;
    const float* W = (sel == 0) ? Wk : (sel == 1) ? Wq : (sel == 2) ? Wv : Ws;
    for (int idx = threadIdx.x; idx < NCP * NC; idx += blockDim.x) {
        int c = idx >> 8, k = idx & 255;
        __nv_bfloat16 h, l; bsplit(W[(size_t)k * NCP + c], h, l);
        g_Wth[sel * NCP * NC + idx] = h;
        g_Wtl[sel * NCP * NC + idx] = l;
    }
}

// ============================================================================
// Kernel 1: projections via bf16 mma 3-product split (unchanged from R11).
// ============================================================================
#define PRJ_SMEM (4 * 128 * SKS * 2)   // 73728 B

__global__ void __launch_bounds__(256) proj_kernel(
    const float* __restrict__ X,
    const float* __restrict__ bk, const float* __restrict__ bq,
    const float* __restrict__ bv, const float* __restrict__ bs,
    float* __restrict__ OutS)
{
    extern __shared__ __align__(16) char smraw[];
    __nv_bfloat16* sXh = (__nv_bfloat16*)smraw;
    __nv_bfloat16* sXl = sXh + 128 * SKS;
    __nv_bfloat16* sWh = sXl + 128 * SKS;
    __nv_bfloat16* sWl = sWh + 128 * SKS;

    const int sel = blockIdx.y;
    const float* bia = (sel == 0) ? bk : (sel == 1) ? bq : (sel == 2) ? bv : bs;
    const __nv_bfloat16* Wh = g_Wth + sel * NCP * NC;
    const __nv_bfloat16* Wl = g_Wtl + sel * NCP * NC;

    const int tid = threadIdx.x;
    const int lane = tid & 31, w = tid >> 5;
    const int g = lane >> 2, q4 = lane & 3;
    const int wm = w & 1, wn = w >> 1;
    const int rowBase = blockIdx.x * 128;

    float C[4][4][4];
#pragma unroll
    for (int mi = 0; mi < 4; mi++)
#pragma unroll
        for (int ni = 0; ni < 4; ni++)
#pragma unroll
            for (int e = 0; e < 4; e++) C[mi][ni][e] = 0.f;

    for (int kp = 0; kp < 4; kp++) {
        __syncthreads();
#pragma unroll
        for (int u = 0; u < 8; u++) {
            int idx = tid + u * 256;
            int r = idx >> 4, c4 = idx & 15;
            float4 v = *(const float4*)(X + (size_t)(rowBase + r) * NC + kp * 64 + c4 * 4);
            __nv_bfloat16 h0,l0,h1,l1,h2,l2,h3,l3;
            bsplit(v.x,h0,l0); bsplit(v.y,h1,l1); bsplit(v.z,h2,l2); bsplit(v.w,h3,l3);
            int so = r * SKS + c4 * 4;
            *(uint2*)(sXh + so) = make_uint2(pk(h0,h1), pk(h2,h3));
            *(uint2*)(sXl + so) = make_uint2(pk(l0,l1), pk(l2,l3));
        }
#pragma unroll
        for (int u = 0; u < 4; u++) {
            int idx = tid + u * 256;
            int col = idx >> 3, k8 = idx & 7;
            int go = col * NC + kp * 64 + k8 * 8;
            int so = col * SKS + k8 * 8;
            *(uint4*)(sWh + so) = *(const uint4*)(Wh + go);
            *(uint4*)(sWl + so) = *(const uint4*)(Wl + go);
        }
        __syncthreads();

#pragma unroll
        for (int kc = 0; kc < 4; kc++) {
            const int k0 = kc * 16 + q4 * 2;
            uint32_t Bh[4][2], Bl[4][2];
#pragma unroll
            for (int ni = 0; ni < 4; ni++) {
                int col = wn * 32 + ni * 8 + g;
                Bh[ni][0] = *(const uint32_t*)(sWh + col * SKS + k0);
                Bh[ni][1] = *(const uint32_t*)(sWh + col * SKS + k0 + 8);
                Bl[ni][0] = *(const uint32_t*)(sWl + col * SKS + k0);
                Bl[ni][1] = *(const uint32_t*)(sWl + col * SKS + k0 + 8);
            }
#pragma unroll
            for (int mi = 0; mi < 4; mi++) {
                int row = wm * 64 + mi * 16 + g;
                uint32_t a0 = *(const uint32_t*)(sXh + row * SKS + k0);
                uint32_t a1 = *(const uint32_t*)(sXh + (row + 8) * SKS + k0);
                uint32_t a2 = *(const uint32_t*)(sXh + row * SKS + k0 + 8);
                uint32_t a3 = *(const uint32_t*)(sXh + (row + 8) * SKS + k0 + 8);
                uint32_t l0 = *(const uint32_t*)(sXl + row * SKS + k0);
                uint32_t l1 = *(const uint32_t*)(sXl + (row + 8) * SKS + k0);
                uint32_t l2 = *(const uint32_t*)(sXl + row * SKS + k0 + 8);
                uint32_t l3 = *(const uint32_t*)(sXl + (row + 8) * SKS + k0 + 8);
#pragma unroll
                for (int ni = 0; ni < 4; ni++) {
                    mma_bf16(C[mi][ni], a0, a1, a2, a3, Bh[ni][0], Bh[ni][1]); // hh
                    mma_bf16(C[mi][ni], a0, a1, a2, a3, Bl[ni][0], Bl[ni][1]); // hl
                    mma_bf16(C[mi][ni], l0, l1, l2, l3, Bh[ni][0], Bh[ni][1]); // lh
                }
            }
        }
    }

#pragma unroll
    for (int ni = 0; ni < 4; ni++) {
        int col = wn * 32 + ni * 8 + q4 * 2;
        float2 bb = *(const float2*)(bia + col);
#pragma unroll
        for (int mi = 0; mi < 4; mi++) {
            int row = rowBase + wm * 64 + mi * 16 + g;
            float v0 = C[mi][ni][0] + bb.x, v1 = C[mi][ni][1] + bb.y;
            float v2 = C[mi][ni][2] + bb.x, v3 = C[mi][ni][3] + bb.y;
            size_t o0 = (size_t)row * NCP + col;
            size_t o1 = (size_t)(row + 8) * NCP + col;
            if (sel <= 1) {
                __nv_bfloat16* Yh = (sel == 0) ? g_Khi : g_Qhi;
                __nv_bfloat16* Yl = (sel == 0) ? g_Klo : g_Qlo;
                __nv_bfloat16 h0,l0,h1,l1;
                bsplit(v0,h0,l0); bsplit(v1,h1,l1);
                *(uint32_t*)(Yh + o0) = pk(h0,h1);
                *(uint32_t*)(Yl + o0) = pk(l0,l1);
                bsplit(v2,h0,l0); bsplit(v3,h1,l1);
                *(uint32_t*)(Yh + o1) = pk(h0,h1);
                *(uint32_t*)(Yl + o1) = pk(l0,l1);
            } else {
                float* Yf = (sel == 2) ? g_V : OutS;
                *(float2*)(Yf + o0) = make_float2(v0, v1);
                *(float2*)(Yf + o1) = make_float2(v2, v3);
            }
        }
    }
}

// ============================================================================
// Kernel 2: V -> V^T bf16 hi/lo  ([b][n][c] f32 -> [b][c][n]).
// ============================================================================
__global__ void vt_kernel()
{
    __shared__ float t[32][33];
    const int b  = blockIdx.z;
    const int n0 = blockIdx.x * 32;
    const int c0 = blockIdx.y * 32;
    const int tx = threadIdx.x, ty = threadIdx.y;   // 32 x 8
#pragma unroll
    for (int u = 0; u < 4; u++)
        t[ty * 4 + u][tx] = g_V[((size_t)b * NN + n0 + ty * 4 + u) * NCP + c0 + tx];
    __syncthreads();
#pragma unroll
    for (int u = 0; u < 4; u++) {
        float x = t[tx][ty * 4 + u];
        __nv_bfloat16 h, l; bsplit(x, h, l);
        size_t off = ((size_t)b * NCP + c0 + ty * 4 + u) * NN + n0 + tx;
        g_Vthi[off] = h;
        g_Vtlo[off] = l;
    }
}

// ============================================================================
// Kernel 3: FUSED flash attention.  O = softmax(K @ Q^T) @ V + shortcut.
//   CTA: 64 K-rows, 4 warps (128 thr), each warp owns 16 rows (FA2-style —
//   softmax needs no cross-warp traffic). Loop 64 chunks of 64 Q-cols.
//   S C-fragment layout == PV A-operand layout (register identity), so P
//   never touches memory. Online softmax, fp32 state. 3-product split on
//   both GEMMs (identical math to R11). smem 104 KB -> 2 CTA/SM.
// ============================================================================
#define FL_SMEM ((4 * 64 * KS2 + 2 * 128 * SKS) * 2)   // 106496 B

__global__ void __launch_bounds__(128) flash_kernel(float* __restrict__ Out)
{
    extern __shared__ __align__(16) char smraw[];
    __nv_bfloat16* sKh = (__nv_bfloat16*)smraw;          // [64][KS2]
    __nv_bfloat16* sKl = sKh + 64 * KS2;
    __nv_bfloat16* sQh = sKl + 64 * KS2;                 // [64][KS2]
    __nv_bfloat16* sQl = sQh + 64 * KS2;
    __nv_bfloat16* sVh = sQl + 64 * KS2;                 // [128][SKS]
    __nv_bfloat16* sVl = sVh + 128 * SKS;

    const int tid = threadIdx.x;
    const int lane = tid & 31, w = tid >> 5;             // 4 warps
    const int g = lane >> 2, t = lane & 3;
    const int mt = blockIdx.x, b = blockIdx.y;

    // ---- load K tile once (64 rows x 128 d, hi+lo) ----
#pragma unroll
    for (int u = 0; u < 8; u++) {
        int idx = tid + u * 128;
        int r = idx >> 4, c8 = idx & 15;
        size_t go = ((size_t)(b * NN + mt * 64 + r)) * NCP + c8 * 8;
        int so = r * KS2 + c8 * 8;
        *(uint4*)(sKh + so) = *(const uint4*)(g_Khi + go);
        *(uint4*)(sKl + so) = *(const uint4*)(g_Klo + go);
    }

    const int rowA = w * 16 + g;                         // warp's A-frag base row

    float Co[16][4];
#pragma unroll
    for (int ci = 0; ci < 16; ci++)
#pragma unroll
        for (int e = 0; e < 4; e++) Co[ci][e] = 0.f;
    float m0 = -1e30f, m1 = -1e30f, l0s = 0.f, l1s = 0.f;

    for (int ch = 0; ch < NN / 64; ch++) {
        __syncthreads();   // prev iter consumers done (also covers K load, iter 0)
        // Q chunk: 64 q-rows x 128 d (B operand for S)
#pragma unroll
        for (int u = 0; u < 8; u++) {
            int idx = tid + u * 128;
            int r = idx >> 4, c8 = idx & 15;
            size_t go = ((size_t)(b * NN + ch * 64 + r)) * NCP + c8 * 8;
            int so = r * KS2 + c8 * 8;
            *(uint4*)(sQh + so) = *(const uint4*)(g_Qhi + go);
            *(uint4*)(sQl + so) = *(const uint4*)(g_Qlo + go);
        }
        // V chunk: 128 c'-rows x 64 n (B operand for PV)
#pragma unroll
        for (int u = 0; u < 8; u++) {
            int idx = tid + u * 128;
            int r = idx >> 3, c8 = idx & 7;
            size_t go = ((size_t)(b * NCP + r)) * NN + ch * 64 + c8 * 8;
            int so = r * SKS + c8 * 8;
            *(uint4*)(sVh + so) = *(const uint4*)(g_Vthi + go);
            *(uint4*)(sVl + so) = *(const uint4*)(g_Vtlo + go);
        }
        __syncthreads();

        // ---- S tile: warp computes S[16 x 64], 3-product split ----
        float Cs[8][4];
#pragma unroll
        for (int ni = 0; ni < 8; ni++)
#pragma unroll
            for (int e = 0; e < 4; e++) Cs[ni][e] = 0.f;
#pragma unroll
        for (int kc = 0; kc < 8; kc++) {
            const int k0 = kc * 16 + t * 2;
            uint32_t a0 = *(const uint32_t*)(sKh + rowA * KS2 + k0);
            uint32_t a1 = *(const uint32_t*)(sKh + (rowA + 8) * KS2 + k0);
            uint32_t a2 = *(const uint32_t*)(sKh + rowA * KS2 + k0 + 8);
            uint32_t a3 = *(const uint32_t*)(sKh + (rowA + 8) * KS2 + k0 + 8);
            uint32_t e0 = *(const uint32_t*)(sKl + rowA * KS2 + k0);
            uint32_t e1 = *(const uint32_t*)(sKl + (rowA + 8) * KS2 + k0);
            uint32_t e2 = *(const uint32_t*)(sKl + rowA * KS2 + k0 + 8);
            uint32_t e3 = *(const uint32_t*)(sKl + (rowA + 8) * KS2 + k0 + 8);
#pragma unroll
            for (int ni = 0; ni < 8; ni++) {
                int col = ni * 8 + g;
                uint32_t bh0 = *(const uint32_t*)(sQh + col * KS2 + k0);
                uint32_t bh1 = *(const uint32_t*)(sQh + col * KS2 + k0 + 8);
                uint32_t bl0 = *(const uint32_t*)(sQl + col * KS2 + k0);
                uint32_t bl1 = *(const uint32_t*)(sQl + col * KS2 + k0 + 8);
                mma_bf16(Cs[ni], a0, a1, a2, a3, bh0, bh1); // hh
                mma_bf16(Cs[ni], a0, a1, a2, a3, bl0, bl1); // hl
                mma_bf16(Cs[ni], e0, e1, e2, e3, bh0, bh1); // lh
            }
        }

        // ---- online softmax (rows g and g+8; row spread over 4 t-lanes) ----
        float mx0 = -1e30f, mx1 = -1e30f;
#pragma unroll
        for (int ni = 0; ni < 8; ni++) {
            mx0 = fmaxf(mx0, fmaxf(Cs[ni][0], Cs[ni][1]));
            mx1 = fmaxf(mx1, fmaxf(Cs[ni][2], Cs[ni][3]));
        }
        mx0 = fmaxf(mx0, __shfl_xor_sync(0xffffffffu, mx0, 1));
        mx0 = fmaxf(mx0, __shfl_xor_sync(0xffffffffu, mx0, 2));
        mx1 = fmaxf(mx1, __shfl_xor_sync(0xffffffffu, mx1, 1));
        mx1 = fmaxf(mx1, __shfl_xor_sync(0xffffffffu, mx1, 2));
        float mn0 = fmaxf(m0, mx0), mn1 = fmaxf(m1, mx1);
        float al0 = __expf(m0 - mn0), al1 = __expf(m1 - mn1);
        m0 = mn0; m1 = mn1;
        float s0 = 0.f, s1 = 0.f;
#pragma unroll
        for (int ni = 0; ni < 8; ni++) {
            Cs[ni][0] = __expf(Cs[ni][0] - mn0);
            Cs[ni][1] = __expf(Cs[ni][1] - mn0);
            Cs[ni][2] = __expf(Cs[ni][2] - mn1);
            Cs[ni][3] = __expf(Cs[ni][3] - mn1);
            s0 += Cs[ni][0] + Cs[ni][1];
            s1 += Cs[ni][2] + Cs[ni][3];
        }
        s0 += __shfl_xor_sync(0xffffffffu, s0, 1);
        s0 += __shfl_xor_sync(0xffffffffu, s0, 2);
        s1 += __shfl_xor_sync(0xffffffffu, s1, 1);
        s1 += __shfl_xor_sync(0xffffffffu, s1, 2);
        l0s = l0s * al0 + s0;
        l1s = l1s * al1 + s1;
#pragma unroll
        for (int ci = 0; ci < 16; ci++) {
            Co[ci][0] *= al0; Co[ci][1] *= al0;
            Co[ci][2] *= al1; Co[ci][3] *= al1;
        }

        // ---- build P A-frags in registers (C-frag == A-frag identity) ----
        uint32_t Ph[4][4], Pl[4][4];
#pragma unroll
        for (int ki = 0; ki < 4; ki++) {
            Ph[ki][0] = pkhi(Cs[2*ki  ][0], Cs[2*ki  ][1]);
            Ph[ki][1] = pkhi(Cs[2*ki  ][2], Cs[2*ki  ][3]);
            Ph[ki][2] = pkhi(Cs[2*ki+1][0], Cs[2*ki+1][1]);
            Ph[ki][3] = pkhi(Cs[2*ki+1][2], Cs[2*ki+1][3]);
            Pl[ki][0] = pklo(Cs[2*ki  ][0], Cs[2*ki  ][1]);
            Pl[ki][1] = pklo(Cs[2*ki  ][2], Cs[2*ki  ][3]);
            Pl[ki][2] = pklo(Cs[2*ki+1][0], Cs[2*ki+1][1]);
            Pl[ki][3] = pklo(Cs[2*ki+1][2], Cs[2*ki+1][3]);
        }

        // ---- O += P @ V (3-product: PhVh + PhVl + PlVh) ----
#pragma unroll
        for (int ks = 0; ks < 4; ks++) {
            const int k0 = ks * 16 + t * 2;
#pragma unroll
            for (int ci = 0; ci < 16; ci++) {
                int col = ci * 8 + g;
                uint32_t vh0 = *(const uint32_t*)(sVh + col * SKS + k0);
                uint32_t vh1 = *(const uint32_t*)(sVh + col * SKS + k0 + 8);
                uint32_t vl0 = *(const uint32_t*)(sVl + col * SKS + k0);
                uint32_t vl1 = *(const uint32_t*)(sVl + col * SKS + k0 + 8);
                mma_bf16(Co[ci], Ph[ks][0], Ph[ks][1], Ph[ks][2], Ph[ks][3], vh0, vh1);
                mma_bf16(Co[ci], Ph[ks][0], Ph[ks][1], Ph[ks][2], Ph[ks][3], vl0, vl1);
                mma_bf16(Co[ci], Pl[ks][0], Pl[ks][1], Pl[ks][2], Pl[ks][3], vh0, vh1);
            }
        }
    }

    // ---- epilogue: Out = O/l + shortcut (Out holds shortcut) ----
    float i0 = 1.0f / l0s, i1 = 1.0f / l1s;
    size_t r0 = (size_t)(b * NN + mt * 64 + rowA) * NCP;
    size_t r1 = (size_t)(b * NN + mt * 64 + rowA + 8) * NCP;
#pragma unroll
    for (int ci = 0; ci < 16; ci++) {
        int col = ci * 8 + t * 2;
        float2 s0v = *(float2*)(Out + r0 + col);
        float2 s1v = *(float2*)(Out + r1 + col);
        *(float2*)(Out + r0 + col) = make_float2(Co[ci][0] * i0 + s0v.x,
                                                 Co[ci][1] * i0 + s0v.y);
        *(float2*)(Out + r1 + col) = make_float2(Co[ci][2] * i1 + s1v.x,
                                                 Co[ci][3] * i1 + s1v.y);
    }
}

// ============================================================================
// Launch
// ============================================================================
extern "C" void kernel_launch(void* const* d_in, const int* in_sizes, int n_in,
                              void* d_out, int out_size) {
    (void)in_sizes; (void)n_in; (void)out_size;
    const float* x  = (const float*)d_in[0];
    const float* Wk = (const float*)d_in[1];
    const float* bk = (const float*)d_in[2];
    const float* Wq = (const float*)d_in[3];
    const float* bq = (const float*)d_in[4];
    const float* Wv = (const float*)d_in[5];
    const float* bv = (const float*)d_in[6];
    const float* Ws = (const float*)d_in[7];
    const float* bs = (const float*)d_in[8];
    float* out = (float*)d_out;

    cudaFuncSetAttribute(proj_kernel,  cudaFuncAttributeMaxDynamicSharedMemorySize, PRJ_SMEM);
    cudaFuncSetAttribute(flash_kernel, cudaFuncAttributeMaxDynamicSharedMemorySize, FL_SMEM);

    // 0) weight pre-split
    wsplit_kernel<<<4, 256>>>(Wk, Wq, Wv, Ws);
    // 1) projections (bf16 mma): K/Q hi-lo, V f32, shortcut -> d_out
    proj_kernel<<<dim3(NB * NN / 128, 4), 256, PRJ_SMEM>>>(x, bk, bq, bv, bs, out);
    // 2) V -> V^T bf16 hi/lo
    vt_kernel<<<dim3(NN / 32, NCP / 32, NB), dim3(32, 8)>>>();
    // 3) fused flash attention (+ shortcut add)
    flash_kernel<<<dim3(NN / 64, NB), 128, FL_SMEM>>>(out);
}

// round 13
// speedup vs baseline: 3.4707x; 1.1130x over previous
#include <cuda_runtime.h>
#include <cuda_bf16.h>
#include <cstdint>

// Problem constants
#define NB  4
#define NN  4096   // H*W
#define NC  256
#define NCP 128

// Scratch (static __device__ arrays: the sanctioned no-alloc scratch mechanism).
static __device__ float          g_V  [NB * NN * NCP];       // fp32 V
static __device__ __nv_bfloat16  g_Khi[NB * NN * NCP];       // K split hi/lo  [b*NN+n][c]
static __device__ __nv_bfloat16  g_Klo[NB * NN * NCP];
static __device__ __nv_bfloat16  g_Qhi[NB * NN * NCP];       // Q split hi/lo
static __device__ __nv_bfloat16  g_Qlo[NB * NN * NCP];
static __device__ __nv_bfloat16  g_Vthi[NB * NCP * NN];      // V^T hi/lo  [b*NCP+c][n]
static __device__ __nv_bfloat16  g_Vtlo[NB * NCP * NN];
static __device__ __nv_bfloat16  g_Wth[4 * NCP * NC];        // W^T splits [sel][col][k]
static __device__ __nv_bfloat16  g_Wtl[4 * NCP * NC];

// ---- bf16 split + pack helpers ----
__device__ __forceinline__ void bsplit(float x, __nv_bfloat16& h, __nv_bfloat16& l) {
    h = __float2bfloat16(x);
    l = __float2bfloat16(x - __bfloat162float(h));
}
__device__ __forceinline__ uint32_t pk(__nv_bfloat16 a, __nv_bfloat16 b) {
    return (uint32_t)__bfloat16_as_ushort(a) | ((uint32_t)__bfloat16_as_ushort(b) << 16);
}
__device__ __forceinline__ uint32_t pkhi(float a, float b) {
    return pk(__float2bfloat16(a), __float2bfloat16(b));
}
__device__ __forceinline__ uint32_t pklo(float a, float b) {
    __nv_bfloat16 ha = __float2bfloat16(a), hb = __float2bfloat16(b);
    return pk(__float2bfloat16(a - __bfloat162float(ha)),
              __float2bfloat16(b - __bfloat162float(hb)));
}

// ---- warp MMA: m16n8k16, row.col, bf16 in, fp32 acc (baseline PTX, sm_80+) ----
__device__ __forceinline__ void mma_bf16(float c[4], uint32_t a0, uint32_t a1,
                                         uint32_t a2, uint32_t a3,
                                         uint32_t b0, uint32_t b1) {
    asm volatile("mma.sync.aligned.m16n8k16.row.col.f32.bf16.bf16.f32 "
        "{%0,%1,%2,%3}, {%4,%5,%6,%7}, {%8,%9}, {%0,%1,%2,%3};"
        : "+f"(c[0]), "+f"(c[1]), "+f"(c[2]), "+f"(c[3])
        : "r"(a0), "r"(a1), "r"(a2), "r"(a3), "r"(b0), "r"(b1));
}

#define SKS 72   // 64-wide tile stride (bf16 elems): conflict-free fragment LDS
#define KS2 136  // 128-wide tile stride: conflict-free

// ============================================================================
// Kernel 0: pre-split + transpose weights: W[k][c] f32 -> [sel][c][k] bf16 hi/lo.
// ============================================================================
__global__ void wsplit_kernel(const float* __restrict__ Wk, const float* __restrict__ Wq,
                              const float* __restrict__ Wv, const float* __restrict__ Ws)
{
    const int sel = blockIdx.x;
    const float* W = (sel == 0) ? Wk : (sel == 1) ? Wq : (sel == 2) ? Wv : Ws;
    for (int idx = threadIdx.x; idx < NCP * NC; idx += blockDim.x) {
        int c = idx >> 8, k = idx & 255;
        __nv_bfloat16 h, l; bsplit(W[(size_t)k * NCP + c], h, l);
        g_Wth[sel * NCP * NC + idx] = h;
        g_Wtl[sel * NCP * NC + idx] = l;
    }
}

// ============================================================================
// Kernel 1: projections via bf16 mma 3-product split (unchanged from R12).
// ============================================================================
#define PRJ_SMEM (4 * 128 * SKS * 2)   // 73728 B

__global__ void __launch_bounds__(256) proj_kernel(
    const float* __restrict__ X,
    const float* __restrict__ bk, const float* __restrict__ bq,
    const float* __restrict__ bv, const float* __restrict__ bs,
    float* __restrict__ OutS)
{
    extern __shared__ __align__(16) char smraw[];
    __nv_bfloat16* sXh = (__nv_bfloat16*)smraw;
    __nv_bfloat16* sXl = sXh + 128 * SKS;
    __nv_bfloat16* sWh = sXl + 128 * SKS;
    __nv_bfloat16* sWl = sWh + 128 * SKS;

    const int sel = blockIdx.y;
    const float* bia = (sel == 0) ? bk : (sel == 1) ? bq : (sel == 2) ? bv : bs;
    const __nv_bfloat16* Wh = g_Wth + sel * NCP * NC;
    const __nv_bfloat16* Wl = g_Wtl + sel * NCP * NC;

    const int tid = threadIdx.x;
    const int lane = tid & 31, w = tid >> 5;
    const int g = lane >> 2, q4 = lane & 3;
    const int wm = w & 1, wn = w >> 1;
    const int rowBase = blockIdx.x * 128;

    float C[4][4][4];
#pragma unroll
    for (int mi = 0; mi < 4; mi++)
#pragma unroll
        for (int ni = 0; ni < 4; ni++)
#pragma unroll
            for (int e = 0; e < 4; e++) C[mi][ni][e] = 0.f;

    for (int kp = 0; kp < 4; kp++) {
        __syncthreads();
#pragma unroll
        for (int u = 0; u < 8; u++) {
            int idx = tid + u * 256;
            int r = idx >> 4, c4 = idx & 15;
            float4 v = *(const float4*)(X + (size_t)(rowBase + r) * NC + kp * 64 + c4 * 4);
            __nv_bfloat16 h0,l0,h1,l1,h2,l2,h3,l3;
            bsplit(v.x,h0,l0); bsplit(v.y,h1,l1); bsplit(v.z,h2,l2); bsplit(v.w,h3,l3);
            int so = r * SKS + c4 * 4;
            *(uint2*)(sXh + so) = make_uint2(pk(h0,h1), pk(h2,h3));
            *(uint2*)(sXl + so) = make_uint2(pk(l0,l1), pk(l2,l3));
        }
#pragma unroll
        for (int u = 0; u < 4; u++) {
            int idx = tid + u * 256;
            int col = idx >> 3, k8 = idx & 7;
            int go = col * NC + kp * 64 + k8 * 8;
            int so = col * SKS + k8 * 8;
            *(uint4*)(sWh + so) = *(const uint4*)(Wh + go);
            *(uint4*)(sWl + so) = *(const uint4*)(Wl + go);
        }
        __syncthreads();

#pragma unroll
        for (int kc = 0; kc < 4; kc++) {
            const int k0 = kc * 16 + q4 * 2;
            uint32_t Bh[4][2], Bl[4][2];
#pragma unroll
            for (int ni = 0; ni < 4; ni++) {
                int col = wn * 32 + ni * 8 + g;
                Bh[ni][0] = *(const uint32_t*)(sWh + col * SKS + k0);
                Bh[ni][1] = *(const uint32_t*)(sWh + col * SKS + k0 + 8);
                Bl[ni][0] = *(const uint32_t*)(sWl + col * SKS + k0);
                Bl[ni][1] = *(const uint32_t*)(sWl + col * SKS + k0 + 8);
            }
#pragma unroll
            for (int mi = 0; mi < 4; mi++) {
                int row = wm * 64 + mi * 16 + g;
                uint32_t a0 = *(const uint32_t*)(sXh + row * SKS + k0);
                uint32_t a1 = *(const uint32_t*)(sXh + (row + 8) * SKS + k0);
                uint32_t a2 = *(const uint32_t*)(sXh + row * SKS + k0 + 8);
                uint32_t a3 = *(const uint32_t*)(sXh + (row + 8) * SKS + k0 + 8);
                uint32_t l0 = *(const uint32_t*)(sXl + row * SKS + k0);
                uint32_t l1 = *(const uint32_t*)(sXl + (row + 8) * SKS + k0);
                uint32_t l2 = *(const uint32_t*)(sXl + row * SKS + k0 + 8);
                uint32_t l3 = *(const uint32_t*)(sXl + (row + 8) * SKS + k0 + 8);
                // product-outer passes (reuse distance 4)
#pragma unroll
                for (int ni = 0; ni < 4; ni++)
                    mma_bf16(C[mi][ni], a0, a1, a2, a3, Bh[ni][0], Bh[ni][1]); // hh
#pragma unroll
                for (int ni = 0; ni < 4; ni++)
                    mma_bf16(C[mi][ni], a0, a1, a2, a3, Bl[ni][0], Bl[ni][1]); // hl
#pragma unroll
                for (int ni = 0; ni < 4; ni++)
                    mma_bf16(C[mi][ni], l0, l1, l2, l3, Bh[ni][0], Bh[ni][1]); // lh
            }
        }
    }

#pragma unroll
    for (int ni = 0; ni < 4; ni++) {
        int col = wn * 32 + ni * 8 + q4 * 2;
        float2 bb = *(const float2*)(bia + col);
#pragma unroll
        for (int mi = 0; mi < 4; mi++) {
            int row = rowBase + wm * 64 + mi * 16 + g;
            float v0 = C[mi][ni][0] + bb.x, v1 = C[mi][ni][1] + bb.y;
            float v2 = C[mi][ni][2] + bb.x, v3 = C[mi][ni][3] + bb.y;
            size_t o0 = (size_t)row * NCP + col;
            size_t o1 = (size_t)(row + 8) * NCP + col;
            if (sel <= 1) {
                __nv_bfloat16* Yh = (sel == 0) ? g_Khi : g_Qhi;
                __nv_bfloat16* Yl = (sel == 0) ? g_Klo : g_Qlo;
                __nv_bfloat16 h0,l0,h1,l1;
                bsplit(v0,h0,l0); bsplit(v1,h1,l1);
                *(uint32_t*)(Yh + o0) = pk(h0,h1);
                *(uint32_t*)(Yl + o0) = pk(l0,l1);
                bsplit(v2,h0,l0); bsplit(v3,h1,l1);
                *(uint32_t*)(Yh + o1) = pk(h0,h1);
                *(uint32_t*)(Yl + o1) = pk(l0,l1);
            } else {
                float* Yf = (sel == 2) ? g_V : OutS;
                *(float2*)(Yf + o0) = make_float2(v0, v1);
                *(float2*)(Yf + o1) = make_float2(v2, v3);
            }
        }
    }
}

// ============================================================================
// Kernel 2: V -> V^T bf16 hi/lo  ([b][n][c] f32 -> [b][c][n]).
// ============================================================================
__global__ void vt_kernel()
{
    __shared__ float t[32][33];
    const int b  = blockIdx.z;
    const int n0 = blockIdx.x * 32;
    const int c0 = blockIdx.y * 32;
    const int tx = threadIdx.x, ty = threadIdx.y;   // 32 x 8
#pragma unroll
    for (int u = 0; u < 4; u++)
        t[ty * 4 + u][tx] = g_V[((size_t)b * NN + n0 + ty * 4 + u) * NCP + c0 + tx];
    __syncthreads();
#pragma unroll
    for (int u = 0; u < 4; u++) {
        float x = t[tx][ty * 4 + u];
        __nv_bfloat16 h, l; bsplit(x, h, l);
        size_t off = ((size_t)b * NCP + c0 + ty * 4 + u) * NN + n0 + tx;
        g_Vthi[off] = h;
        g_Vtlo[off] = l;
    }
}

// ============================================================================
// Kernel 3: FUSED flash attention with chain-broken mma scheduling.
//   Identical math to R12; only the issue order changed: the 3 split products
//   are separate passes over the tile index, so consecutive volatile mmas hit
//   DIFFERENT accumulators (reuse distance 8 in S, 16 in PV) and HMMA latency
//   is hidden even at 8 warps/SM. Softmax rescale skipped when alpha == 1.
// ============================================================================
#define FL_SMEM ((4 * 64 * KS2 + 2 * 128 * SKS) * 2)   // 106496 B

__global__ void __launch_bounds__(128) flash_kernel(float* __restrict__ Out)
{
    extern __shared__ __align__(16) char smraw[];
    __nv_bfloat16* sKh = (__nv_bfloat16*)smraw;          // [64][KS2]
    __nv_bfloat16* sKl = sKh + 64 * KS2;
    __nv_bfloat16* sQh = sKl + 64 * KS2;                 // [64][KS2]
    __nv_bfloat16* sQl = sQh + 64 * KS2;
    __nv_bfloat16* sVh = sQl + 64 * KS2;                 // [128][SKS]
    __nv_bfloat16* sVl = sVh + 128 * SKS;

    const int tid = threadIdx.x;
    const int lane = tid & 31, w = tid >> 5;             // 4 warps
    const int g = lane >> 2, t = lane & 3;
    const int mt = blockIdx.x, b = blockIdx.y;

    // ---- load K tile once (64 rows x 128 d, hi+lo) ----
#pragma unroll
    for (int u = 0; u < 8; u++) {
        int idx = tid + u * 128;
        int r = idx >> 4, c8 = idx & 15;
        size_t go = ((size_t)(b * NN + mt * 64 + r)) * NCP + c8 * 8;
        int so = r * KS2 + c8 * 8;
        *(uint4*)(sKh + so) = *(const uint4*)(g_Khi + go);
        *(uint4*)(sKl + so) = *(const uint4*)(g_Klo + go);
    }

    const int rowA = w * 16 + g;                         // warp's A-frag base row

    float Co[16][4];
#pragma unroll
    for (int ci = 0; ci < 16; ci++)
#pragma unroll
        for (int e = 0; e < 4; e++) Co[ci][e] = 0.f;
    float m0 = -1e30f, m1 = -1e30f, l0s = 0.f, l1s = 0.f;

    for (int ch = 0; ch < NN / 64; ch++) {
        __syncthreads();
        // Q chunk: 64 q-rows x 128 d
#pragma unroll
        for (int u = 0; u < 8; u++) {
            int idx = tid + u * 128;
            int r = idx >> 4, c8 = idx & 15;
            size_t go = ((size_t)(b * NN + ch * 64 + r)) * NCP + c8 * 8;
            int so = r * KS2 + c8 * 8;
            *(uint4*)(sQh + so) = *(const uint4*)(g_Qhi + go);
            *(uint4*)(sQl + so) = *(const uint4*)(g_Qlo + go);
        }
        // V chunk: 128 c'-rows x 64 n
#pragma unroll
        for (int u = 0; u < 8; u++) {
            int idx = tid + u * 128;
            int r = idx >> 3, c8 = idx & 7;
            size_t go = ((size_t)(b * NCP + r)) * NN + ch * 64 + c8 * 8;
            int so = r * SKS + c8 * 8;
            *(uint4*)(sVh + so) = *(const uint4*)(g_Vthi + go);
            *(uint4*)(sVl + so) = *(const uint4*)(g_Vtlo + go);
        }
        __syncthreads();

        // ---- S tile: product-outer passes (accumulator reuse distance 8) ----
        float Cs[8][4];
#pragma unroll
        for (int ni = 0; ni < 8; ni++)
#pragma unroll
            for (int e = 0; e < 4; e++) Cs[ni][e] = 0.f;
#pragma unroll
        for (int kc = 0; kc < 8; kc++) {
            const int k0 = kc * 16 + t * 2;
            uint32_t a0 = *(const uint32_t*)(sKh + rowA * KS2 + k0);
            uint32_t a1 = *(const uint32_t*)(sKh + (rowA + 8) * KS2 + k0);
            uint32_t a2 = *(const uint32_t*)(sKh + rowA * KS2 + k0 + 8);
            uint32_t a3 = *(const uint32_t*)(sKh + (rowA + 8) * KS2 + k0 + 8);
            uint32_t e0 = *(const uint32_t*)(sKl + rowA * KS2 + k0);
            uint32_t e1 = *(const uint32_t*)(sKl + (rowA + 8) * KS2 + k0);
            uint32_t e2 = *(const uint32_t*)(sKl + rowA * KS2 + k0 + 8);
            uint32_t e3 = *(const uint32_t*)(sKl + (rowA + 8) * KS2 + k0 + 8);
#pragma unroll
            for (int ni = 0; ni < 8; ni++) {                       // pass 1: hh
                int col = ni * 8 + g;
                uint32_t bh0 = *(const uint32_t*)(sQh + col * KS2 + k0);
                uint32_t bh1 = *(const uint32_t*)(sQh + col * KS2 + k0 + 8);
                mma_bf16(Cs[ni], a0, a1, a2, a3, bh0, bh1);
            }
#pragma unroll
            for (int ni = 0; ni < 8; ni++) {                       // pass 2: hl
                int col = ni * 8 + g;
                uint32_t bl0 = *(const uint32_t*)(sQl + col * KS2 + k0);
                uint32_t bl1 = *(const uint32_t*)(sQl + col * KS2 + k0 + 8);
                mma_bf16(Cs[ni], a0, a1, a2, a3, bl0, bl1);
            }
#pragma unroll
            for (int ni = 0; ni < 8; ni++) {                       // pass 3: lh
                int col = ni * 8 + g;
                uint32_t bh0 = *(const uint32_t*)(sQh + col * KS2 + k0);
                uint32_t bh1 = *(const uint32_t*)(sQh + col * KS2 + k0 + 8);
                mma_bf16(Cs[ni], e0, e1, e2, e3, bh0, bh1);
            }
        }

        // ---- online softmax (rows g and g+8; row spread over 4 t-lanes) ----
        float mx0 = -1e30f, mx1 = -1e30f;
#pragma unroll
        for (int ni = 0; ni < 8; ni++) {
            mx0 = fmaxf(mx0, fmaxf(Cs[ni][0], Cs[ni][1]));
            mx1 = fmaxf(mx1, fmaxf(Cs[ni][2], Cs[ni][3]));
        }
        mx0 = fmaxf(mx0, __shfl_xor_sync(0xffffffffu, mx0, 1));
        mx0 = fmaxf(mx0, __shfl_xor_sync(0xffffffffu, mx0, 2));
        mx1 = fmaxf(mx1, __shfl_xor_sync(0xffffffffu, mx1, 1));
        mx1 = fmaxf(mx1, __shfl_xor_sync(0xffffffffu, mx1, 2));
        float mn0 = fmaxf(m0, mx0), mn1 = fmaxf(m1, mx1);
        if (mn0 > m0 || mn1 > m1) {             // rescale only when max advanced
            float al0 = __expf(m0 - mn0), al1 = __expf(m1 - mn1);
            l0s *= al0; l1s *= al1;
#pragma unroll
            for (int ci = 0; ci < 16; ci++) {
                Co[ci][0] *= al0; Co[ci][1] *= al0;
                Co[ci][2] *= al1; Co[ci][3] *= al1;
            }
            m0 = mn0; m1 = mn1;
        }
        float s0 = 0.f, s1 = 0.f;
#pragma unroll
        for (int ni = 0; ni < 8; ni++) {
            Cs[ni][0] = __expf(Cs[ni][0] - m0);
            Cs[ni][1] = __expf(Cs[ni][1] - m0);
            Cs[ni][2] = __expf(Cs[ni][2] - m1);
            Cs[ni][3] = __expf(Cs[ni][3] - m1);
            s0 += Cs[ni][0] + Cs[ni][1];
            s1 += Cs[ni][2] + Cs[ni][3];
        }
        s0 += __shfl_xor_sync(0xffffffffu, s0, 1);
        s0 += __shfl_xor_sync(0xffffffffu, s0, 2);
        s1 += __shfl_xor_sync(0xffffffffu, s1, 1);
        s1 += __shfl_xor_sync(0xffffffffu, s1, 2);
        l0s += s0;
        l1s += s1;

        // ---- build P A-frags in registers (C-frag == A-frag identity) ----
        uint32_t Ph[4][4], Pl[4][4];
#pragma unroll
        for (int ki = 0; ki < 4; ki++) {
            Ph[ki][0] = pkhi(Cs[2*ki  ][0], Cs[2*ki  ][1]);
            Ph[ki][1] = pkhi(Cs[2*ki  ][2], Cs[2*ki  ][3]);
            Ph[ki][2] = pkhi(Cs[2*ki+1][0], Cs[2*ki+1][1]);
            Ph[ki][3] = pkhi(Cs[2*ki+1][2], Cs[2*ki+1][3]);
            Pl[ki][0] = pklo(Cs[2*ki  ][0], Cs[2*ki  ][1]);
            Pl[ki][1] = pklo(Cs[2*ki  ][2], Cs[2*ki  ][3]);
            Pl[ki][2] = pklo(Cs[2*ki+1][0], Cs[2*ki+1][1]);
            Pl[ki][3] = pklo(Cs[2*ki+1][2], Cs[2*ki+1][3]);
        }

        // ---- O += P @ V: product-outer passes (reuse distance 16) ----
#pragma unroll
        for (int ks = 0; ks < 4; ks++) {
            const int k0 = ks * 16 + t * 2;
#pragma unroll
            for (int ci = 0; ci < 16; ci++) {                      // pass 1: PhVh
                int col = ci * 8 + g;
                uint32_t vh0 = *(const uint32_t*)(sVh + col * SKS + k0);
                uint32_t vh1 = *(const uint32_t*)(sVh + col * SKS + k0 + 8);
                mma_bf16(Co[ci], Ph[ks][0], Ph[ks][1], Ph[ks][2], Ph[ks][3], vh0, vh1);
            }
#pragma unroll
            for (int ci = 0; ci < 16; ci++) {                      // pass 2: PhVl
                int col = ci * 8 + g;
                uint32_t vl0 = *(const uint32_t*)(sVl + col * SKS + k0);
                uint32_t vl1 = *(const uint32_t*)(sVl + col * SKS + k0 + 8);
                mma_bf16(Co[ci], Ph[ks][0], Ph[ks][1], Ph[ks][2], Ph[ks][3], vl0, vl1);
            }
#pragma unroll
            for (int ci = 0; ci < 16; ci++) {                      // pass 3: PlVh
                int col = ci * 8 + g;
                uint32_t vh0 = *(const uint32_t*)(sVh + col * SKS + k0);
                uint32_t vh1 = *(const uint32_t*)(sVh + col * SKS + k0 + 8);
                mma_bf16(Co[ci], Pl[ks][0], Pl[ks][1], Pl[ks][2], Pl[ks][3], vh0, vh1);
            }
        }
    }

    // ---- epilogue: Out = O/l + shortcut (Out holds shortcut) ----
    float i0 = 1.0f / l0s, i1 = 1.0f / l1s;
    size_t r0 = (size_t)(b * NN + mt * 64 + rowA) * NCP;
    size_t r1 = (size_t)(b * NN + mt * 64 + rowA + 8) * NCP;
#pragma unroll
    for (int ci = 0; ci < 16; ci++) {
        int col = ci * 8 + t * 2;
        float2 s0v = *(float2*)(Out + r0 + col);
        float2 s1v = *(float2*)(Out + r1 + col);
        *(float2*)(Out + r0 + col) = make_float2(Co[ci][0] * i0 + s0v.x,
                                                 Co[ci][1] * i0 + s0v.y);
        *(float2*)(Out + r1 + col) = make_float2(Co[ci][2] * i1 + s1v.x,
                                                 Co[ci][3] * i1 + s1v.y);
    }
}

// ============================================================================
// Launch
// ============================================================================
extern "C" void kernel_launch(void* const* d_in, const int* in_sizes, int n_in,
                              void* d_out, int out_size) {
    (void)in_sizes; (void)n_in; (void)out_size;
    const float* x  = (const float*)d_in[0];
    const float* Wk = (const float*)d_in[1];
    const float* bk = (const float*)d_in[2];
    const float* Wq = (const float*)d_in[3];
    const float* bq = (const float*)d_in[4];
    const float* Wv = (const float*)d_in[5];
    const float* bv = (const float*)d_in[6];
    const float* Ws = (const float*)d_in[7];
    const float* bs = (const float*)d_in[8];
    float* out = (float*)d_out;

    cudaFuncSetAttribute(proj_kernel,  cudaFuncAttributeMaxDynamicSharedMemorySize, PRJ_SMEM);
    cudaFuncSetAttribute(flash_kernel, cudaFuncAttributeMaxDynamicSharedMemorySize, FL_SMEM);

    // 0) weight pre-split
    wsplit_kernel<<<4, 256>>>(Wk, Wq, Wv, Ws);
    // 1) projections (bf16 mma): K/Q hi-lo, V f32, shortcut -> d_out
    proj_kernel<<<dim3(NB * NN / 128, 4), 256, PRJ_SMEM>>>(x, bk, bq, bv, bs, out);
    // 2) V -> V^T bf16 hi/lo
    vt_kernel<<<dim3(NN / 32, NCP / 32, NB), dim3(32, 8)>>>();
    // 3) fused flash attention (+ shortcut add)
    flash_kernel<<<dim3(NN / 64, NB), 128, FL_SMEM>>>(out);
}